// round 2
// baseline (speedup 1.0000x reference)
#include <cuda_runtime.h>

typedef unsigned long long ull;

#define Nn 64
#define C1 512
#define C2 128
#define C3 32
#define HW 784
#define NPIX (Nn*HW)   // 50176

#define FMAXV 3.402823466e38f

// ---------------- device scratch ----------------
__device__ float g_a1[C1], g_b1v[C1], g_a2[C2], g_b2v[C2];
__device__ float g_wq1t[C1*C2];          // quantized w1, transposed [ci][co]
__device__ float g_wq2[C3*C2*9];         // quantized w2, original layout
__device__ float g_h2buf[Nn*C2*HW];      // relu(BN2(y1)), pre-quant (25.7 MB)
__device__ unsigned g_h1mn, g_h1mx, g_h2mn, g_h2mx;  // nonneg floats as uint bits

// ---------------- f32x2 helpers ----------------
__device__ __forceinline__ ull pack2(float lo, float hi) {
    ull r; asm("mov.b64 %0, {%1,%2};" : "=l"(r) : "f"(lo), "f"(hi)); return r;
}
__device__ __forceinline__ float2 unpack2(ull v) {
    float2 r; asm("mov.b64 {%0,%1}, %2;" : "=f"(r.x), "=f"(r.y) : "l"(v)); return r;
}
__device__ __forceinline__ ull ffma2(ull a, ull b, ull c) {
    ull d; asm("fma.rn.f32x2 %0, %1, %2, %3;" : "=l"(d) : "l"(a), "l"(b), "l"(c)); return d;
}

__device__ __forceinline__ float wredmin(float v) {
    #pragma unroll
    for (int o = 16; o > 0; o >>= 1) v = fminf(v, __shfl_xor_sync(0xffffffffu, v, o));
    return v;
}
__device__ __forceinline__ float wredmax(float v) {
    #pragma unroll
    for (int o = 16; o > 0; o >>= 1) v = fmaxf(v, __shfl_xor_sync(0xffffffffu, v, o));
    return v;
}

__device__ __forceinline__ float fq(float x, float mn, float s) {
    // round-half-even, IEEE divide regardless of fast-math
    return fmaf(rintf(__fdiv_rn(x - mn, s)), s, mn);
}

// ---------------- 1: prep (BN affine + reset stats) ----------------
__global__ void prep_k(const float* __restrict__ g1, const float* __restrict__ b1,
                       const float* __restrict__ m1, const float* __restrict__ v1,
                       const float* __restrict__ g2, const float* __restrict__ b2,
                       const float* __restrict__ m2, const float* __restrict__ v2) {
    int t = threadIdx.x;
    if (t == 0) { g_h1mn = 0x7f7fffffu; g_h1mx = 0u; g_h2mn = 0x7f7fffffu; g_h2mx = 0u; }
    if (t < C1) {
        float inv = g1[t] / sqrtf(v1[t] + 1e-5f);
        g_a1[t] = inv; g_b1v[t] = b1[t] - m1[t] * inv;
    }
    if (t < C2) {
        float inv = g2[t] / sqrtf(v2[t] + 1e-5f);
        g_a2[t] = inv; g_b2v[t] = b2[t] - m2[t] * inv;
    }
}

// ---------------- 2: weight fake-quant (block 0: w1->transposed, block 1: w2) ----------------
__global__ void wquant_k(const float* __restrict__ w1, const float* __restrict__ w2) {
    __shared__ float smn[256], smx[256];
    int which = blockIdx.x, t = threadIdx.x;
    const float* w = which ? w2 : w1;
    int n = which ? C3 * C2 * 9 : C2 * C1;
    float mn = FMAXV, mx = -FMAXV;
    for (int i = t; i < n; i += 256) { float v = w[i]; mn = fminf(mn, v); mx = fmaxf(mx, v); }
    smn[t] = mn; smx[t] = mx; __syncthreads();
    for (int s = 128; s > 0; s >>= 1) {
        if (t < s) { smn[t] = fminf(smn[t], smn[t + s]); smx[t] = fmaxf(smx[t], smx[t + s]); }
        __syncthreads();
    }
    float mnv = smn[0];
    float sc = fmaxf((smx[0] - mnv) * (1.f / 255.f), 1e-8f);
    if (which == 0) {
        for (int i = t; i < n; i += 256) {
            float q = fq(w1[i], mnv, sc);
            int co = i >> 9, ci = i & 511;
            g_wq1t[ci * C2 + co] = q;
        }
    } else {
        for (int i = t; i < n; i += 256) g_wq2[i] = fq(w2[i], mnv, sc);
    }
}

// ---------------- 3: global min/max of relu(BN1(x)) ----------------
__global__ void h1mm_k(const float* __restrict__ x) {
    const int NV = Nn * C1 * HW / 4;   // vec4 elements; 784 % 4 == 0
    float mn = FMAXV, mx = 0.f;
    for (int v = blockIdx.x * blockDim.x + threadIdx.x; v < NV; v += gridDim.x * blockDim.x) {
        int ci = (v / 196) & 511;      // 196 vec4 per 28x28 plane
        float4 p = ((const float4*)x)[v];
        float a = g_a1[ci], b = g_b1v[ci];
        float h0 = fmaxf(fmaf(a, p.x, b), 0.f);
        float h1 = fmaxf(fmaf(a, p.y, b), 0.f);
        float h2 = fmaxf(fmaf(a, p.z, b), 0.f);
        float h3 = fmaxf(fmaf(a, p.w, b), 0.f);
        mn = fminf(mn, fminf(fminf(h0, h1), fminf(h2, h3)));
        mx = fmaxf(mx, fmaxf(fmaxf(h0, h1), fmaxf(h2, h3)));
    }
    __shared__ float smn[8], smx[8];
    float bm = wredmin(mn), bM = wredmax(mx);
    int w = threadIdx.x >> 5, ln = threadIdx.x & 31;
    if (ln == 0) { smn[w] = bm; smx[w] = bM; }
    __syncthreads();
    if (w == 0) {
        float m2 = (ln < 8) ? smn[ln] : FMAXV;
        float M2 = (ln < 8) ? smx[ln] : 0.f;
        m2 = wredmin(m2); M2 = wredmax(M2);
        if (ln == 0) {
            atomicMin(&g_h1mn, __float_as_uint(m2));
            atomicMax(&g_h1mx, __float_as_uint(M2));
        }
    }
}

// ---------------- 4: conv1x1 as GEMM (f32x2), fused BN1+relu+quant on load,
//                    fused BN2+relu + h2 min/max in epilogue ----------------
__global__ __launch_bounds__(256) void conv1_k(const float* __restrict__ x) {
    __shared__ __align__(16) float As[16 * 128];   // wq1t chunk [k][co]
    __shared__ __align__(16) float Bs[16][68];     // quantized activations [k][pix]
    __shared__ float smn[8], smx[8];

    const int tid = threadIdx.x, tx = tid & 15, ty = tid >> 4;
    const int col0 = blockIdx.x * 64;
    const float mn1 = __uint_as_float(g_h1mn);
    const float mx1 = __uint_as_float(g_h1mx);
    const float s1 = fmaxf((mx1 - mn1) * (1.f / 255.f), 1e-8f);

    ull acc[4][4];
    #pragma unroll
    for (int i = 0; i < 4; i++)
        #pragma unroll
        for (int j = 0; j < 4; j++) acc[i][j] = 0ull;

    for (int k0 = 0; k0 < C1; k0 += 16) {
        // A: contiguous copy of 16 rows of wq1t (coalesced float4)
        #pragma unroll
        for (int l = 0; l < 2; l++) {
            int e = tid + l * 256;
            ((float4*)As)[e] = ((const float4*)(g_wq1t + k0 * 128))[e];
        }
        // B: BN1 + relu + fake-quant on the fly
        #pragma unroll
        for (int l = 0; l < 4; l++) {
            int e = tid + l * 256;
            int k = e >> 6, nn = e & 63;
            int gp = col0 + nn;
            int nimg = gp / 784;
            int p = gp - nimg * 784;
            int ci = k0 + k;
            float v = x[(nimg * C1 + ci) * HW + p];
            float h = fmaxf(fmaf(g_a1[ci], v, g_b1v[ci]), 0.f);
            Bs[k][nn] = fq(h, mn1, s1);
        }
        __syncthreads();
        #pragma unroll
        for (int k = 0; k < 16; k++) {
            const ull* ar = (const ull*)(As + k * 128);
            ull a0 = ar[ty], a1p = ar[ty + 16], a2p = ar[ty + 32], a3p = ar[ty + 48];
            float4 bv = *(const float4*)&Bs[k][tx * 4];
            ull b0 = pack2(bv.x, bv.x), b1p = pack2(bv.y, bv.y);
            ull b2p = pack2(bv.z, bv.z), b3p = pack2(bv.w, bv.w);
            acc[0][0] = ffma2(a0, b0, acc[0][0]);
            acc[0][1] = ffma2(a0, b1p, acc[0][1]);
            acc[0][2] = ffma2(a0, b2p, acc[0][2]);
            acc[0][3] = ffma2(a0, b3p, acc[0][3]);
            acc[1][0] = ffma2(a1p, b0, acc[1][0]);
            acc[1][1] = ffma2(a1p, b1p, acc[1][1]);
            acc[1][2] = ffma2(a1p, b2p, acc[1][2]);
            acc[1][3] = ffma2(a1p, b3p, acc[1][3]);
            acc[2][0] = ffma2(a2p, b0, acc[2][0]);
            acc[2][1] = ffma2(a2p, b1p, acc[2][1]);
            acc[2][2] = ffma2(a2p, b2p, acc[2][2]);
            acc[2][3] = ffma2(a2p, b3p, acc[2][3]);
            acc[3][0] = ffma2(a3p, b0, acc[3][0]);
            acc[3][1] = ffma2(a3p, b1p, acc[3][1]);
            acc[3][2] = ffma2(a3p, b2p, acc[3][2]);
            acc[3][3] = ffma2(a3p, b3p, acc[3][3]);
        }
        __syncthreads();
    }

    // epilogue: h2 = relu(BN2(y1)), store + min/max
    int gp0 = col0 + tx * 4;
    int nimg = gp0 / 784;
    int p0 = gp0 - nimg * 784;      // 4 consecutive pixels never cross an image (784%4==0)
    float lmn = FMAXV, lmx = 0.f;
    #pragma unroll
    for (int i = 0; i < 4; i++) {
        int cb = 2 * (ty + 16 * i);
        float2 v0 = unpack2(acc[i][0]), v1 = unpack2(acc[i][1]);
        float2 v2 = unpack2(acc[i][2]), v3 = unpack2(acc[i][3]);
        #pragma unroll
        for (int u = 0; u < 2; u++) {
            float a2c = g_a2[cb + u], b2c = g_b2v[cb + u];
            float4 o;
            o.x = fmaxf(fmaf(a2c, u ? v0.y : v0.x, b2c), 0.f);
            o.y = fmaxf(fmaf(a2c, u ? v1.y : v1.x, b2c), 0.f);
            o.z = fmaxf(fmaf(a2c, u ? v2.y : v2.x, b2c), 0.f);
            o.w = fmaxf(fmaf(a2c, u ? v3.y : v3.x, b2c), 0.f);
            lmn = fminf(lmn, fminf(fminf(o.x, o.y), fminf(o.z, o.w)));
            lmx = fmaxf(lmx, fmaxf(fmaxf(o.x, o.y), fmaxf(o.z, o.w)));
            *(float4*)(g_h2buf + (nimg * C2 + cb + u) * HW + p0) = o;
        }
    }
    float bm = wredmin(lmn), bM = wredmax(lmx);
    int w = tid >> 5, ln = tid & 31;
    if (ln == 0) { smn[w] = bm; smx[w] = bM; }
    __syncthreads();
    if (w == 0) {
        float m2 = (ln < 8) ? smn[ln] : FMAXV;
        float M2 = (ln < 8) ? smx[ln] : 0.f;
        m2 = wredmin(m2); M2 = wredmax(M2);
        if (ln == 0) {
            atomicMin(&g_h2mn, __float_as_uint(m2));
            atomicMax(&g_h2mx, __float_as_uint(M2));
        }
    }
}

// ---------------- 5: conv3x3 (pad 1), quantize input on smem load, f32x2 co-pairs ----------------
__global__ __launch_bounds__(256) void conv2_k(float* __restrict__ out) {
    __shared__ float tile[30 * 33];   // 30x30 padded input plane, stride 33 (bank decorrelation)
    __shared__ ull wsm[4][9];         // co-pair packed 3x3 weights for this ci
    const int tid = threadIdx.x;
    const int n = blockIdx.y, cog = blockIdx.x;   // 8 output channels per block
    const float mn2 = __uint_as_float(g_h2mn);
    const float mx2 = __uint_as_float(g_h2mx);
    const float s2 = fmaxf((mx2 - mn2) * (1.f / 255.f), 1e-8f);

    ull acc[4][4];
    #pragma unroll
    for (int c = 0; c < 4; c++)
        #pragma unroll
        for (int j = 0; j < 4; j++) acc[c][j] = 0ull;

    const int p0 = tid * 4;                 // 4 consecutive pixels, same row (28%4==0)
    const int r0 = p0 / 28, c0 = p0 - (p0 / 28) * 28;

    for (int ci = 0; ci < C2; ci++) {
        if (tid < 36) {
            int c = tid / 9, k = tid - c * 9;
            int co = cog * 8 + 2 * c;
            float wa = g_wq2[(co * C2 + ci) * 9 + k];
            float wb = g_wq2[((co + 1) * C2 + ci) * 9 + k];
            wsm[c][k] = pack2(wa, wb);
        }
        const float* src = g_h2buf + (n * C2 + ci) * HW;
        for (int e = tid; e < 900; e += 256) {
            int r = e / 30, cc = e - r * 30;
            float v = 0.f;                  // zero padding of the QUANTIZED tensor: exact
            int rr = r - 1, c2 = cc - 1;
            if ((unsigned)rr < 28u && (unsigned)c2 < 28u)
                v = fq(src[rr * 28 + c2], mn2, s2);
            tile[r * 33 + cc] = v;
        }
        __syncthreads();
        if (tid < 196) {
            #pragma unroll
            for (int dr = 0; dr < 3; dr++) {
                float rv[6];
                #pragma unroll
                for (int q = 0; q < 6; q++) rv[q] = tile[(r0 + dr) * 33 + c0 + q];
                #pragma unroll
                for (int dc = 0; dc < 3; dc++) {
                    int k = dr * 3 + dc;
                    ull w0 = wsm[0][k], w1 = wsm[1][k], w2v = wsm[2][k], w3 = wsm[3][k];
                    #pragma unroll
                    for (int j = 0; j < 4; j++) {
                        ull tt = pack2(rv[dc + j], rv[dc + j]);
                        acc[0][j] = ffma2(w0, tt, acc[0][j]);
                        acc[1][j] = ffma2(w1, tt, acc[1][j]);
                        acc[2][j] = ffma2(w2v, tt, acc[2][j]);
                        acc[3][j] = ffma2(w3, tt, acc[3][j]);
                    }
                }
            }
        }
        __syncthreads();
    }
    if (tid < 196) {
        #pragma unroll
        for (int c = 0; c < 4; c++) {
            float2 v0 = unpack2(acc[c][0]), v1 = unpack2(acc[c][1]);
            float2 v2 = unpack2(acc[c][2]), v3 = unpack2(acc[c][3]);
            int co = cog * 8 + 2 * c;
            float4 oa = { v0.x, v1.x, v2.x, v3.x };
            float4 ob = { v0.y, v1.y, v2.y, v3.y };
            *(float4*)(out + (n * C3 + co) * HW + p0) = oa;
            *(float4*)(out + (n * C3 + co + 1) * HW + p0) = ob;
        }
    }
}

// ---------------- launch ----------------
extern "C" void kernel_launch(void* const* d_in, const int* in_sizes, int n_in,
                              void* d_out, int out_size) {
    const float* x  = (const float*)d_in[0];
    const float* g1 = (const float*)d_in[1];
    const float* b1 = (const float*)d_in[2];
    const float* m1 = (const float*)d_in[3];
    const float* v1 = (const float*)d_in[4];
    const float* w1 = (const float*)d_in[5];
    const float* g2 = (const float*)d_in[6];
    const float* b2 = (const float*)d_in[7];
    const float* m2 = (const float*)d_in[8];
    const float* v2 = (const float*)d_in[9];
    const float* w2 = (const float*)d_in[10];
    float* out = (float*)d_out;

    prep_k<<<1, 512>>>(g1, b1, m1, v1, g2, b2, m2, v2);
    wquant_k<<<2, 256>>>(w1, w2);
    h1mm_k<<<2048, 256>>>(x);
    conv1_k<<<NPIX / 64, 256>>>(x);
    conv2_k<<<dim3(4, Nn), 256>>>(out);
}

// round 3
// speedup vs baseline: 1.1518x; 1.1518x over previous
#include <cuda_runtime.h>

typedef unsigned long long ull;

#define Nn 64
#define C1 512
#define C2 128
#define C3 32
#define HW 784
#define NPIX (Nn*HW)   // 50176

#define FMAXV 3.402823466e38f

// ---------------- device scratch ----------------
__device__ float g_a1[C1], g_b1v[C1], g_a2[C2], g_b2v[C2];
__device__ float g_wq1t[C1*C2];                 // quantized w1, transposed [ci][co]
__device__ float g_wq2[C3*C2*9];                // quantized w2, original layout
__device__ ull   g_wq2p[4*C2*36];               // packed co-pair weights [cog][ci][k*4+c]
__device__ __align__(16) float g_h2buf[Nn*C2*HW];  // relu(BN2(y1)); quantized in-place by h2q_k
__device__ unsigned g_h1mn, g_h1mx, g_h2mn, g_h2mx;  // nonneg floats as uint bits

// ---------------- f32x2 helpers ----------------
__device__ __forceinline__ ull pack2(float lo, float hi) {
    ull r; asm("mov.b64 %0, {%1,%2};" : "=l"(r) : "f"(lo), "f"(hi)); return r;
}
__device__ __forceinline__ float2 unpack2(ull v) {
    float2 r; asm("mov.b64 {%0,%1}, %2;" : "=f"(r.x), "=f"(r.y) : "l"(v)); return r;
}
__device__ __forceinline__ ull ffma2(ull a, ull b, ull c) {
    ull d; asm("fma.rn.f32x2 %0, %1, %2, %3;" : "=l"(d) : "l"(a), "l"(b), "l"(c)); return d;
}

__device__ __forceinline__ float wredmin(float v) {
    #pragma unroll
    for (int o = 16; o > 0; o >>= 1) v = fminf(v, __shfl_xor_sync(0xffffffffu, v, o));
    return v;
}
__device__ __forceinline__ float wredmax(float v) {
    #pragma unroll
    for (int o = 16; o > 0; o >>= 1) v = fmaxf(v, __shfl_xor_sync(0xffffffffu, v, o));
    return v;
}

__device__ __forceinline__ float fq_div(float x, float mn, float s) {
    // exact IEEE divide path (weights only; cheap)
    return fmaf(rintf(__fdiv_rn(x - mn, s)), s, mn);
}
__device__ __forceinline__ float fq_inv(float x, float mn, float s, float inv) {
    return fmaf(rintf((x - mn) * inv), s, mn);
}

// ---------------- 1: prep (BN affine + reset stats) ----------------
__global__ void prep_k(const float* __restrict__ g1, const float* __restrict__ b1,
                       const float* __restrict__ m1, const float* __restrict__ v1,
                       const float* __restrict__ g2, const float* __restrict__ b2,
                       const float* __restrict__ m2, const float* __restrict__ v2) {
    int t = threadIdx.x;
    if (t == 0) { g_h1mn = 0x7f7fffffu; g_h1mx = 0u; g_h2mn = 0x7f7fffffu; g_h2mx = 0u; }
    if (t < C1) {
        float inv = g1[t] / sqrtf(v1[t] + 1e-5f);
        g_a1[t] = inv; g_b1v[t] = b1[t] - m1[t] * inv;
    }
    if (t < C2) {
        float inv = g2[t] / sqrtf(v2[t] + 1e-5f);
        g_a2[t] = inv; g_b2v[t] = b2[t] - m2[t] * inv;
    }
}

// ---------------- 2: weight fake-quant; block 0: w1->transposed, block 1: w2 + pack ----------------
__global__ void wquant_k(const float* __restrict__ w1, const float* __restrict__ w2) {
    __shared__ float smn[256], smx[256];
    int which = blockIdx.x, t = threadIdx.x;
    const float* w = which ? w2 : w1;
    int n = which ? C3 * C2 * 9 : C2 * C1;
    float mn = FMAXV, mx = -FMAXV;
    for (int i = t; i < n; i += 256) { float v = w[i]; mn = fminf(mn, v); mx = fmaxf(mx, v); }
    smn[t] = mn; smx[t] = mx; __syncthreads();
    for (int s = 128; s > 0; s >>= 1) {
        if (t < s) { smn[t] = fminf(smn[t], smn[t + s]); smx[t] = fmaxf(smx[t], smx[t + s]); }
        __syncthreads();
    }
    float mnv = smn[0];
    float sc = fmaxf((smx[0] - mnv) * (1.f / 255.f), 1e-8f);
    if (which == 0) {
        for (int i = t; i < n; i += 256) {
            float q = fq_div(w1[i], mnv, sc);
            int co = i >> 9, ci = i & 511;
            g_wq1t[ci * C2 + co] = q;
        }
    } else {
        for (int i = t; i < n; i += 256) g_wq2[i] = fq_div(w2[i], mnv, sc);
        __syncthreads();   // make g_wq2 visible within block, then pack co-pairs
        for (int f = t; f < 4 * C2 * 36; f += 256) {
            int cog = f / (C2 * 36);
            int r   = f - cog * (C2 * 36);
            int ci  = r / 36;
            int m   = r - ci * 36;
            int k   = m >> 2, c = m & 3;
            int co  = cog * 8 + 2 * c;
            float wa = g_wq2[(co * C2 + ci) * 9 + k];
            float wb = g_wq2[((co + 1) * C2 + ci) * 9 + k];
            g_wq2p[f] = pack2(wa, wb);
        }
    }
}

// ---------------- 3: global min/max of relu(BN1(x)) ----------------
__global__ void h1mm_k(const float* __restrict__ x) {
    const int NV = Nn * C1 * HW / 4;   // vec4 elements; 784 % 4 == 0
    float mn = FMAXV, mx = 0.f;
    for (int v = blockIdx.x * blockDim.x + threadIdx.x; v < NV; v += gridDim.x * blockDim.x) {
        int ci = (v / 196) & 511;      // 196 vec4 per 28x28 plane
        float4 p = ((const float4*)x)[v];
        float a = g_a1[ci], b = g_b1v[ci];
        float h0 = fmaxf(fmaf(a, p.x, b), 0.f);
        float h1 = fmaxf(fmaf(a, p.y, b), 0.f);
        float h2 = fmaxf(fmaf(a, p.z, b), 0.f);
        float h3 = fmaxf(fmaf(a, p.w, b), 0.f);
        mn = fminf(mn, fminf(fminf(h0, h1), fminf(h2, h3)));
        mx = fmaxf(mx, fmaxf(fmaxf(h0, h1), fmaxf(h2, h3)));
    }
    __shared__ float smn[8], smx[8];
    float bm = wredmin(mn), bM = wredmax(mx);
    int w = threadIdx.x >> 5, ln = threadIdx.x & 31;
    if (ln == 0) { smn[w] = bm; smx[w] = bM; }
    __syncthreads();
    if (w == 0) {
        float m2 = (ln < 8) ? smn[ln] : FMAXV;
        float M2 = (ln < 8) ? smx[ln] : 0.f;
        m2 = wredmin(m2); M2 = wredmax(M2);
        if (ln == 0) {
            atomicMin(&g_h1mn, __float_as_uint(m2));
            atomicMax(&g_h1mx, __float_as_uint(M2));
        }
    }
}

// ---------------- 4: conv1x1 as GEMM (f32x2), fused BN1+relu+quant on load,
//                    fused BN2+relu + h2 min/max in epilogue ----------------
__global__ __launch_bounds__(256) void conv1_k(const float* __restrict__ x) {
    __shared__ __align__(16) float As[16 * 128];   // wq1t chunk [k][co]
    __shared__ __align__(16) float Bs[16][68];     // quantized activations [k][pix]
    __shared__ float smn[8], smx[8];

    const int tid = threadIdx.x, tx = tid & 15, ty = tid >> 4;
    const int col0 = blockIdx.x * 64;
    const float mn1 = __uint_as_float(g_h1mn);
    const float mx1 = __uint_as_float(g_h1mx);
    const float s1 = fmaxf((mx1 - mn1) * (1.f / 255.f), 1e-8f);
    const float i1 = 1.f / s1;

    // hoist B-fill index math out of the k-chunk loop
    int xbase[4], kk[4], nn[4], nimgl[4], pl[4];
    #pragma unroll
    for (int l = 0; l < 4; l++) {
        int e = tid + l * 256;
        kk[l] = e >> 6; nn[l] = e & 63;
        int gp = col0 + nn[l];
        int nimg = gp / 784;
        int p = gp - nimg * 784;
        nimgl[l] = nimg; pl[l] = p;
        xbase[l] = nimg * C1 * HW + p;
    }

    ull acc[4][4];
    #pragma unroll
    for (int i = 0; i < 4; i++)
        #pragma unroll
        for (int j = 0; j < 4; j++) acc[i][j] = 0ull;

    for (int k0 = 0; k0 < C1; k0 += 16) {
        // A: contiguous copy of 16 rows of wq1t (coalesced float4)
        #pragma unroll
        for (int l = 0; l < 2; l++) {
            int e = tid + l * 256;
            ((float4*)As)[e] = ((const float4*)(g_wq1t + k0 * 128))[e];
        }
        // B: BN1 + relu + fake-quant on the fly
        #pragma unroll
        for (int l = 0; l < 4; l++) {
            int ci = k0 + kk[l];
            float v = x[xbase[l] + ci * HW];
            float h = fmaxf(fmaf(g_a1[ci], v, g_b1v[ci]), 0.f);
            Bs[kk[l]][nn[l]] = fq_inv(h, mn1, s1, i1);
        }
        __syncthreads();
        #pragma unroll
        for (int k = 0; k < 16; k++) {
            const ull* ar = (const ull*)(As + k * 128);
            ull a0 = ar[ty], a1p = ar[ty + 16], a2p = ar[ty + 32], a3p = ar[ty + 48];
            float4 bv = *(const float4*)&Bs[k][tx * 4];
            ull b0 = pack2(bv.x, bv.x), b1p = pack2(bv.y, bv.y);
            ull b2p = pack2(bv.z, bv.z), b3p = pack2(bv.w, bv.w);
            acc[0][0] = ffma2(a0, b0, acc[0][0]);
            acc[0][1] = ffma2(a0, b1p, acc[0][1]);
            acc[0][2] = ffma2(a0, b2p, acc[0][2]);
            acc[0][3] = ffma2(a0, b3p, acc[0][3]);
            acc[1][0] = ffma2(a1p, b0, acc[1][0]);
            acc[1][1] = ffma2(a1p, b1p, acc[1][1]);
            acc[1][2] = ffma2(a1p, b2p, acc[1][2]);
            acc[1][3] = ffma2(a1p, b3p, acc[1][3]);
            acc[2][0] = ffma2(a2p, b0, acc[2][0]);
            acc[2][1] = ffma2(a2p, b1p, acc[2][1]);
            acc[2][2] = ffma2(a2p, b2p, acc[2][2]);
            acc[2][3] = ffma2(a2p, b3p, acc[2][3]);
            acc[3][0] = ffma2(a3p, b0, acc[3][0]);
            acc[3][1] = ffma2(a3p, b1p, acc[3][1]);
            acc[3][2] = ffma2(a3p, b2p, acc[3][2]);
            acc[3][3] = ffma2(a3p, b3p, acc[3][3]);
        }
        __syncthreads();
    }

    // epilogue: h2 = relu(BN2(y1)), store + min/max
    int gp0 = col0 + tx * 4;
    int nimg = gp0 / 784;
    int p0 = gp0 - nimg * 784;      // 4 consecutive pixels never cross an image (784%4==0)
    float lmn = FMAXV, lmx = 0.f;
    #pragma unroll
    for (int i = 0; i < 4; i++) {
        int cb = 2 * (ty + 16 * i);
        float2 v0 = unpack2(acc[i][0]), v1 = unpack2(acc[i][1]);
        float2 v2 = unpack2(acc[i][2]), v3 = unpack2(acc[i][3]);
        #pragma unroll
        for (int u = 0; u < 2; u++) {
            float a2c = g_a2[cb + u], b2c = g_b2v[cb + u];
            float4 o;
            o.x = fmaxf(fmaf(a2c, u ? v0.y : v0.x, b2c), 0.f);
            o.y = fmaxf(fmaf(a2c, u ? v1.y : v1.x, b2c), 0.f);
            o.z = fmaxf(fmaf(a2c, u ? v2.y : v2.x, b2c), 0.f);
            o.w = fmaxf(fmaf(a2c, u ? v3.y : v3.x, b2c), 0.f);
            lmn = fminf(lmn, fminf(fminf(o.x, o.y), fminf(o.z, o.w)));
            lmx = fmaxf(lmx, fmaxf(fmaxf(o.x, o.y), fmaxf(o.z, o.w)));
            *(float4*)(g_h2buf + (nimg * C2 + cb + u) * HW + p0) = o;
        }
    }
    float bm = wredmin(lmn), bM = wredmax(lmx);
    int w = tid >> 5, ln = tid & 31;
    if (ln == 0) { smn[w] = bm; smx[w] = bM; }
    __syncthreads();
    if (w == 0) {
        float m2 = (ln < 8) ? smn[ln] : FMAXV;
        float M2 = (ln < 8) ? smx[ln] : 0.f;
        m2 = wredmin(m2); M2 = wredmax(M2);
        if (ln == 0) {
            atomicMin(&g_h2mn, __float_as_uint(m2));
            atomicMax(&g_h2mx, __float_as_uint(M2));
        }
    }
}

// ---------------- 4.5: quantize h2 in place (vec4) ----------------
__global__ __launch_bounds__(256) void h2q_k() {
    const int NV = Nn * C2 * HW / 4;
    int i = blockIdx.x * 256 + threadIdx.x;
    if (i >= NV) return;
    const float mn = __uint_as_float(g_h2mn);
    const float mx = __uint_as_float(g_h2mx);
    const float s = fmaxf((mx - mn) * (1.f / 255.f), 1e-8f);
    const float inv = 1.f / s;
    float4 v = ((const float4*)g_h2buf)[i];
    v.x = fq_inv(v.x, mn, s, inv);
    v.y = fq_inv(v.y, mn, s, inv);
    v.z = fq_inv(v.z, mn, s, inv);
    v.w = fq_inv(v.w, mn, s, inv);
    ((float4*)g_h2buf)[i] = v;
}

// ---------------- 5: conv3x3 (pad 1), double-buffered tile, pre-quantized input ----------------
__global__ __launch_bounds__(256) void conv2_k(float* __restrict__ out) {
    __shared__ float tile[2][30 * 33];  // padded 30x30 plane, row stride 33
    __shared__ ull wsm[C2 * 36];        // all weights for this cog: [ci][k*4+c] co-pairs

    const int tid = threadIdx.x;
    const int n = blockIdx.y, cog = blockIdx.x;

    // stage all weights for this cog (36.8 KB, once per block)
    for (int f = tid; f < C2 * 36; f += 256) wsm[f] = g_wq2p[cog * C2 * 36 + f];

    // per-thread load slots (fixed across ci)
    int si[4], go[4];
    #pragma unroll
    for (int s = 0; s < 4; s++) {
        int e = tid + 256 * s;
        if (e < 900) {
            int r = e / 30, cc = e - r * 30;
            si[s] = r * 33 + cc;
            int rr = r - 1, c2 = cc - 1;
            go[s] = ((unsigned)rr < 28u && (unsigned)c2 < 28u) ? rr * 28 + c2 : -1;
        } else { si[s] = -1; go[s] = -1; }
    }
    const float* base = g_h2buf + n * C2 * HW;

    // prologue: tile for ci = 0
    #pragma unroll
    for (int s = 0; s < 4; s++)
        if (si[s] >= 0) tile[0][si[s]] = (go[s] >= 0) ? base[go[s]] : 0.f;

    ull acc[4][4];
    #pragma unroll
    for (int c = 0; c < 4; c++)
        #pragma unroll
        for (int j = 0; j < 4; j++) acc[c][j] = 0ull;

    const int p0 = tid * 4;                 // 4 consecutive pixels, same row (28%4==0)
    const int r0 = p0 / 28, c0 = p0 - (p0 / 28) * 28;

    __syncthreads();

    for (int ci = 0; ci < C2; ci++) {
        const int cur = ci & 1;
        // issue next-plane loads early; compute hides their latency
        float v[4];
        if (ci < C2 - 1) {
            const float* src = base + (ci + 1) * HW;
            #pragma unroll
            for (int s = 0; s < 4; s++)
                v[s] = (go[s] >= 0) ? src[go[s]] : 0.f;
        }
        if (tid < 196) {
            const ull* wrow = wsm + ci * 36;
            #pragma unroll
            for (int dr = 0; dr < 3; dr++) {
                const float* trow = &tile[cur][(r0 + dr) * 33 + c0];
                ull tv[6];
                #pragma unroll
                for (int q = 0; q < 6; q++) tv[q] = pack2(trow[q], trow[q]);
                #pragma unroll
                for (int dc = 0; dc < 3; dc++) {
                    const int k = dr * 3 + dc;
                    ulonglong2 wa = *(const ulonglong2*)(wrow + k * 4);
                    ulonglong2 wb = *(const ulonglong2*)(wrow + k * 4 + 2);
                    #pragma unroll
                    for (int j = 0; j < 4; j++) {
                        acc[0][j] = ffma2(wa.x, tv[dc + j], acc[0][j]);
                        acc[1][j] = ffma2(wa.y, tv[dc + j], acc[1][j]);
                        acc[2][j] = ffma2(wb.x, tv[dc + j], acc[2][j]);
                        acc[3][j] = ffma2(wb.y, tv[dc + j], acc[3][j]);
                    }
                }
            }
        }
        if (ci < C2 - 1) {
            const int nxt = cur ^ 1;
            #pragma unroll
            for (int s = 0; s < 4; s++)
                if (si[s] >= 0) tile[nxt][si[s]] = v[s];
        }
        __syncthreads();
    }

    if (tid < 196) {
        #pragma unroll
        for (int c = 0; c < 4; c++) {
            float2 v0 = unpack2(acc[c][0]), v1 = unpack2(acc[c][1]);
            float2 v2 = unpack2(acc[c][2]), v3 = unpack2(acc[c][3]);
            int co = cog * 8 + 2 * c;
            float4 oa = { v0.x, v1.x, v2.x, v3.x };
            float4 ob = { v0.y, v1.y, v2.y, v3.y };
            *(float4*)(out + (n * C3 + co) * HW + p0) = oa;
            *(float4*)(out + (n * C3 + co + 1) * HW + p0) = ob;
        }
    }
}

// ---------------- launch ----------------
extern "C" void kernel_launch(void* const* d_in, const int* in_sizes, int n_in,
                              void* d_out, int out_size) {
    const float* x  = (const float*)d_in[0];
    const float* g1 = (const float*)d_in[1];
    const float* b1 = (const float*)d_in[2];
    const float* m1 = (const float*)d_in[3];
    const float* v1 = (const float*)d_in[4];
    const float* w1 = (const float*)d_in[5];
    const float* g2 = (const float*)d_in[6];
    const float* b2 = (const float*)d_in[7];
    const float* m2 = (const float*)d_in[8];
    const float* v2 = (const float*)d_in[9];
    const float* w2 = (const float*)d_in[10];
    float* out = (float*)d_out;

    prep_k<<<1, 512>>>(g1, b1, m1, v1, g2, b2, m2, v2);
    wquant_k<<<2, 256>>>(w1, w2);
    h1mm_k<<<2048, 256>>>(x);
    conv1_k<<<NPIX / 64, 256>>>(x);
    h2q_k<<<(Nn * C2 * HW / 4 + 255) / 256, 256>>>();
    conv2_k<<<dim3(4, Nn), 256>>>(out);
}

// round 4
// speedup vs baseline: 2.1952x; 1.9059x over previous
#include <cuda_runtime.h>

typedef unsigned long long ull;

#define Nn 64
#define C1 512
#define C2 128
#define C3 32
#define HW 784
#define NPIX (Nn*HW)   // 50176

#define FMAXV 3.402823466e38f

// ---------------- device scratch ----------------
__device__ float g_a1[C1], g_b1v[C1], g_a2[C2], g_b2v[C2];
__device__ uint4 g_w1p[8*16*32];                // w1 u8 codes, mma-fragment-permuted
__device__ float g_j1row[C2];                   // per-co sum of w1 codes
__device__ float g_w1mn, g_w1s;                 // w1 quant params
__device__ float g_wq2[C3*C2*9];                // quantized w2, original layout
__device__ ull   g_wq2p[4*C2*36];               // packed co-pair weights [cog][ci][k*4+c]
__device__ __align__(16) float g_h2buf[Nn*C2*HW];  // relu(BN2(y1)); quantized in-place by h2q_k
__device__ unsigned g_h1mn, g_h1mx, g_h2mn, g_h2mx;  // nonneg floats as uint bits

// ---------------- helpers ----------------
__device__ __forceinline__ ull pack2(float lo, float hi) {
    ull r; asm("mov.b64 %0, {%1,%2};" : "=l"(r) : "f"(lo), "f"(hi)); return r;
}
__device__ __forceinline__ float2 unpack2(ull v) {
    float2 r; asm("mov.b64 {%0,%1}, %2;" : "=f"(r.x), "=f"(r.y) : "l"(v)); return r;
}
__device__ __forceinline__ ull ffma2(ull a, ull b, ull c) {
    ull d; asm("fma.rn.f32x2 %0, %1, %2, %3;" : "=l"(d) : "l"(a), "l"(b), "l"(c)); return d;
}
__device__ __forceinline__ void mma_u8(int* d, unsigned a0, unsigned a1, unsigned a2, unsigned a3,
                                       unsigned b0, unsigned b1) {
    asm volatile("mma.sync.aligned.m16n8k32.row.col.s32.u8.u8.s32 "
                 "{%0,%1,%2,%3},{%4,%5,%6,%7},{%8,%9},{%0,%1,%2,%3};"
                 : "+r"(d[0]), "+r"(d[1]), "+r"(d[2]), "+r"(d[3])
                 : "r"(a0), "r"(a1), "r"(a2), "r"(a3), "r"(b0), "r"(b1));
}

__device__ __forceinline__ float wredmin(float v) {
    #pragma unroll
    for (int o = 16; o > 0; o >>= 1) v = fminf(v, __shfl_xor_sync(0xffffffffu, v, o));
    return v;
}
__device__ __forceinline__ float wredmax(float v) {
    #pragma unroll
    for (int o = 16; o > 0; o >>= 1) v = fmaxf(v, __shfl_xor_sync(0xffffffffu, v, o));
    return v;
}

__device__ __forceinline__ float fq_div(float x, float mn, float s) {
    return fmaf(rintf(__fdiv_rn(x - mn, s)), s, mn);
}
__device__ __forceinline__ float fq_inv(float x, float mn, float s, float inv) {
    return fmaf(rintf((x - mn) * inv), s, mn);
}

// ---------------- 1: prep (BN affine + reset stats) ----------------
__global__ void prep_k(const float* __restrict__ g1, const float* __restrict__ b1,
                       const float* __restrict__ m1, const float* __restrict__ v1,
                       const float* __restrict__ g2, const float* __restrict__ b2,
                       const float* __restrict__ m2, const float* __restrict__ v2) {
    int t = threadIdx.x;
    if (t == 0) { g_h1mn = 0x7f7fffffu; g_h1mx = 0u; g_h2mn = 0x7f7fffffu; g_h2mx = 0u; }
    if (t < C1) {
        float inv = g1[t] / sqrtf(v1[t] + 1e-5f);
        g_a1[t] = inv; g_b1v[t] = b1[t] - m1[t] * inv;
    }
    if (t < C2) {
        float inv = g2[t] / sqrtf(v2[t] + 1e-5f);
        g_a2[t] = inv; g_b2v[t] = b2[t] - m2[t] * inv;
    }
}

// ---------------- 2: weight fake-quant ----------------
// block 0: w1 -> u8 codes (mma-permuted) + Jrow + params ; block 1: w2 quant + co-pair pack
__global__ void wquant_k(const float* __restrict__ w1, const float* __restrict__ w2) {
    __shared__ float smn[256], smx[256];
    int which = blockIdx.x, t = threadIdx.x;
    const float* w = which ? w2 : w1;
    int n = which ? C3 * C2 * 9 : C2 * C1;
    float mn = FMAXV, mx = -FMAXV;
    for (int i = t; i < n; i += 256) { float v = w[i]; mn = fminf(mn, v); mx = fmaxf(mx, v); }
    smn[t] = mn; smx[t] = mx; __syncthreads();
    for (int s = 128; s > 0; s >>= 1) {
        if (t < s) { smn[t] = fminf(smn[t], smn[t + s]); smx[t] = fmaxf(smx[t], smx[t + s]); }
        __syncthreads();
    }
    float mnv = smn[0];
    float sc = fmaxf((smx[0] - mnv) * (1.f / 255.f), 1e-8f);
    if (which == 0) {
        if (t == 0) { g_w1mn = mnv; g_w1s = sc; }
        // permuted fragment codes: f indexes (m, q, L)
        for (int f = t; f < 8 * 16 * 32; f += 256) {
            int m = f >> 9;
            int rem = f & 511;
            int q = rem >> 5, L = rem & 31;
            unsigned rg[4];
            #pragma unroll
            for (int r = 0; r < 4; r++) {
                int row = m * 16 + (L >> 2) + (r & 1) * 8;
                int kc = q * 32 + (r >> 1) * 16 + (L & 3) * 4;
                unsigned u = 0;
                #pragma unroll
                for (int i = 0; i < 4; i++) {
                    int code = __float2int_rn(__fdiv_rn(w1[row * C1 + kc + i] - mnv, sc));
                    u |= ((unsigned)code & 0xffu) << (8 * i);
                }
                rg[r] = u;
            }
            g_w1p[f] = make_uint4(rg[0], rg[1], rg[2], rg[3]);
        }
        // per-co code sums
        if (t < C2) {
            int s = 0;
            for (int ci = 0; ci < C1; ci++)
                s += __float2int_rn(__fdiv_rn(w1[t * C1 + ci] - mnv, sc));
            g_j1row[t] = (float)s;
        }
    } else {
        for (int i = t; i < n; i += 256) g_wq2[i] = fq_div(w2[i], mnv, sc);
        __syncthreads();
        for (int f = t; f < 4 * C2 * 36; f += 256) {
            int cog = f / (C2 * 36);
            int r   = f - cog * (C2 * 36);
            int ci  = r / 36;
            int m   = r - ci * 36;
            int k   = m >> 2, c = m & 3;
            int co  = cog * 8 + 2 * c;
            float wa = g_wq2[(co * C2 + ci) * 9 + k];
            float wb = g_wq2[((co + 1) * C2 + ci) * 9 + k];
            g_wq2p[f] = pack2(wa, wb);
        }
    }
}

// ---------------- 3: global min/max of relu(BN1(x)) ----------------
__global__ void h1mm_k(const float* __restrict__ x) {
    const int NV = Nn * C1 * HW / 4;
    float mn = FMAXV, mx = 0.f;
    for (int v = blockIdx.x * blockDim.x + threadIdx.x; v < NV; v += gridDim.x * blockDim.x) {
        int ci = (v / 196) & 511;
        float4 p = ((const float4*)x)[v];
        float a = g_a1[ci], b = g_b1v[ci];
        float h0 = fmaxf(fmaf(a, p.x, b), 0.f);
        float h1 = fmaxf(fmaf(a, p.y, b), 0.f);
        float h2 = fmaxf(fmaf(a, p.z, b), 0.f);
        float h3 = fmaxf(fmaf(a, p.w, b), 0.f);
        mn = fminf(mn, fminf(fminf(h0, h1), fminf(h2, h3)));
        mx = fmaxf(mx, fmaxf(fmaxf(h0, h1), fmaxf(h2, h3)));
    }
    __shared__ float smn[8], smx[8];
    float bm = wredmin(mn), bM = wredmax(mx);
    int w = threadIdx.x >> 5, ln = threadIdx.x & 31;
    if (ln == 0) { smn[w] = bm; smx[w] = bM; }
    __syncthreads();
    if (w == 0) {
        float m2 = (ln < 8) ? smn[ln] : FMAXV;
        float M2 = (ln < 8) ? smx[ln] : 0.f;
        m2 = wredmin(m2); M2 = wredmax(M2);
        if (ln == 0) {
            atomicMin(&g_h1mn, __float_as_uint(m2));
            atomicMax(&g_h1mx, __float_as_uint(M2));
        }
    }
}

// ---------------- 4: conv1x1 via u8 IMMA tensor cores ----------------
// y = sw*s1*S + mnw*s1*Kcol[p] + sw*mn1*Jrow[co] + 512*mnw*mn1 ; S exact int8 GEMM.
#define BPITCH 80
__global__ __launch_bounds__(256) void conv1_k(const float* __restrict__ x) {
    __shared__ __align__(16) unsigned char Bs[64 * BPITCH];
    __shared__ int kcp[4][64];
    __shared__ float kcolF[64];
    __shared__ float sa1[C1], sb1[C1];
    __shared__ float smn[8], smx[8];

    const int tid = threadIdx.x;
    const int lane = tid & 31, wid = tid >> 5;
    const int col0 = blockIdx.x * 64;

    // stage BN1 params
    #pragma unroll
    for (int l = 0; l < 2; l++) {
        int e = tid + l * 256;
        sa1[e] = g_a1[e]; sb1[e] = g_b1v[e];
    }

    const float mn1 = __uint_as_float(g_h1mn);
    const float mx1 = __uint_as_float(g_h1mx);
    const float s1 = fmaxf((mx1 - mn1) * (1.f / 255.f), 1e-8f);
    const float i1 = 1.f / s1;

    // B-fill geometry: fixed pixel per thread, 16 ci per chunk
    const int pB = tid & 63;
    const int tq = tid >> 6;
    const int gpB = col0 + pB;
    const int nimgB = gpB / 784;
    const float* xb = x + nimgB * C1 * HW + (gpB - nimgB * 784);

    int acc[8][4];
    #pragma unroll
    for (int t = 0; t < 8; t++)
        #pragma unroll
        for (int r = 0; r < 4; r++) acc[t][r] = 0;

    float v[16];
    #pragma unroll
    for (int i = 0; i < 16; i++) {
        int ci = ((i >> 2) * 4 + tq) * 4 + (i & 3);
        v[i] = xb[ci * HW];
    }
    int ksum = 0;
    __syncthreads();   // sa1/sb1 ready

    for (int c = 0; c < 8; c++) {
        // quantize staged regs -> u8 codes into Bs[pB][*]
        #pragma unroll
        for (int s = 0; s < 4; s++) {
            unsigned u = 0;
            #pragma unroll
            for (int j = 0; j < 4; j++) {
                int ci = c * 64 + (s * 4 + tq) * 4 + j;
                float h = fmaxf(fmaf(sa1[ci], v[s * 4 + j], sb1[ci]), 0.f);
                int code = __float2int_rn((h - mn1) * i1);
                ksum += code;
                u |= ((unsigned)code & 0xffu) << (8 * j);
            }
            *(unsigned*)(Bs + pB * BPITCH + (s * 4 + tq) * 4) = u;
        }
        __syncthreads();
        // prefetch next chunk
        if (c < 7) {
            #pragma unroll
            for (int i = 0; i < 16; i++) {
                int ci = (c + 1) * 64 + ((i >> 2) * 4 + tq) * 4 + (i & 3);
                v[i] = xb[ci * HW];
            }
        }
        // mma: 2 k32 steps on this chunk
        #pragma unroll
        for (int q2 = 0; q2 < 2; q2++) {
            int q = c * 2 + q2;
            uint4 a = g_w1p[(wid * 16 + q) * 32 + lane];
            const unsigned char* bbase = Bs + (lane >> 2) * BPITCH + q2 * 32 + (lane & 3) * 4;
            #pragma unroll
            for (int t = 0; t < 8; t++) {
                unsigned b0 = *(const unsigned*)(bbase + t * 8 * BPITCH);
                unsigned b1 = *(const unsigned*)(bbase + t * 8 * BPITCH + 16);
                mma_u8(acc[t], a.x, a.y, a.z, a.w, b0, b1);
            }
        }
        __syncthreads();
    }

    kcp[tq][pB] = ksum;
    __syncthreads();
    if (tid < 64) kcolF[tid] = (float)(kcp[0][tid] + kcp[1][tid] + kcp[2][tid] + kcp[3][tid]);
    __syncthreads();

    // epilogue
    const float sw = g_w1s, mnw = g_w1mn;
    const float cS = sw * s1;
    const float cK = mnw * s1;
    const float cJ = sw * mn1;
    const float cD = 512.f * mnw * mn1;

    const int g = lane >> 2;
    const int co0 = wid * 16 + g, co1 = co0 + 8;
    const float base0 = fmaf(cJ, g_j1row[co0], cD);
    const float base1 = fmaf(cJ, g_j1row[co1], cD);
    const float a20 = g_a2[co0], b20 = g_b2v[co0];
    const float a21 = g_a2[co1], b21 = g_b2v[co1];

    float lmn = FMAXV, lmx = 0.f;
    #pragma unroll
    for (int t = 0; t < 8; t++) {
        int pl = t * 8 + (lane & 3) * 2;
        float kc0 = kcolF[pl], kc1 = kcolF[pl + 1];
        float y00 = fmaf(cS, __int2float_rn(acc[t][0]), fmaf(cK, kc0, base0));
        float y01 = fmaf(cS, __int2float_rn(acc[t][1]), fmaf(cK, kc1, base0));
        float y10 = fmaf(cS, __int2float_rn(acc[t][2]), fmaf(cK, kc0, base1));
        float y11 = fmaf(cS, __int2float_rn(acc[t][3]), fmaf(cK, kc1, base1));
        float h00 = fmaxf(fmaf(a20, y00, b20), 0.f);
        float h01 = fmaxf(fmaf(a20, y01, b20), 0.f);
        float h10 = fmaxf(fmaf(a21, y10, b21), 0.f);
        float h11 = fmaxf(fmaf(a21, y11, b21), 0.f);
        lmn = fminf(lmn, fminf(fminf(h00, h01), fminf(h10, h11)));
        lmx = fmaxf(lmx, fmaxf(fmaxf(h00, h01), fmaxf(h10, h11)));
        int gp0 = col0 + pl, gp1 = gp0 + 1;
        int n0 = gp0 / 784, p0 = gp0 - n0 * 784;
        int n1 = gp1 / 784, p1 = gp1 - n1 * 784;
        g_h2buf[(n0 * C2 + co0) * HW + p0] = h00;
        g_h2buf[(n1 * C2 + co0) * HW + p1] = h01;
        g_h2buf[(n0 * C2 + co1) * HW + p0] = h10;
        g_h2buf[(n1 * C2 + co1) * HW + p1] = h11;
    }
    float bm = wredmin(lmn), bM = wredmax(lmx);
    if (lane == 0) { smn[wid] = bm; smx[wid] = bM; }
    __syncthreads();
    if (wid == 0) {
        float m2 = (lane < 8) ? smn[lane] : FMAXV;
        float M2 = (lane < 8) ? smx[lane] : 0.f;
        m2 = wredmin(m2); M2 = wredmax(M2);
        if (lane == 0) {
            atomicMin(&g_h2mn, __float_as_uint(m2));
            atomicMax(&g_h2mx, __float_as_uint(M2));
        }
    }
}

// ---------------- 4.5: quantize h2 in place (vec4) ----------------
__global__ __launch_bounds__(256) void h2q_k() {
    const int NV = Nn * C2 * HW / 4;
    int i = blockIdx.x * 256 + threadIdx.x;
    if (i >= NV) return;
    const float mn = __uint_as_float(g_h2mn);
    const float mx = __uint_as_float(g_h2mx);
    const float s = fmaxf((mx - mn) * (1.f / 255.f), 1e-8f);
    const float inv = 1.f / s;
    float4 v = ((const float4*)g_h2buf)[i];
    v.x = fq_inv(v.x, mn, s, inv);
    v.y = fq_inv(v.y, mn, s, inv);
    v.z = fq_inv(v.z, mn, s, inv);
    v.w = fq_inv(v.w, mn, s, inv);
    ((float4*)g_h2buf)[i] = v;
}

// ---------------- 5: conv3x3 (pad 1), double-buffered tile, pre-quantized input ----------------
__global__ __launch_bounds__(256) void conv2_k(float* __restrict__ out) {
    __shared__ float tile[2][30 * 33];
    __shared__ ull wsm[C2 * 36];

    const int tid = threadIdx.x;
    const int n = blockIdx.y, cog = blockIdx.x;

    for (int f = tid; f < C2 * 36; f += 256) wsm[f] = g_wq2p[cog * C2 * 36 + f];

    int si[4], go[4];
    #pragma unroll
    for (int s = 0; s < 4; s++) {
        int e = tid + 256 * s;
        if (e < 900) {
            int r = e / 30, cc = e - r * 30;
            si[s] = r * 33 + cc;
            int rr = r - 1, c2 = cc - 1;
            go[s] = ((unsigned)rr < 28u && (unsigned)c2 < 28u) ? rr * 28 + c2 : -1;
        } else { si[s] = -1; go[s] = -1; }
    }
    const float* base = g_h2buf + n * C2 * HW;

    #pragma unroll
    for (int s = 0; s < 4; s++)
        if (si[s] >= 0) tile[0][si[s]] = (go[s] >= 0) ? base[go[s]] : 0.f;

    ull acc[4][4];
    #pragma unroll
    for (int c = 0; c < 4; c++)
        #pragma unroll
        for (int j = 0; j < 4; j++) acc[c][j] = 0ull;

    const int p0 = tid * 4;
    const int r0 = p0 / 28, c0 = p0 - (p0 / 28) * 28;

    __syncthreads();

    for (int ci = 0; ci < C2; ci++) {
        const int cur = ci & 1;
        float v[4];
        if (ci < C2 - 1) {
            const float* src = base + (ci + 1) * HW;
            #pragma unroll
            for (int s = 0; s < 4; s++)
                v[s] = (go[s] >= 0) ? src[go[s]] : 0.f;
        }
        if (tid < 196) {
            const ull* wrow = wsm + ci * 36;
            #pragma unroll
            for (int dr = 0; dr < 3; dr++) {
                const float* trow = &tile[cur][(r0 + dr) * 33 + c0];
                ull tv[6];
                #pragma unroll
                for (int q = 0; q < 6; q++) tv[q] = pack2(trow[q], trow[q]);
                #pragma unroll
                for (int dc = 0; dc < 3; dc++) {
                    const int k = dr * 3 + dc;
                    ulonglong2 wa = *(const ulonglong2*)(wrow + k * 4);
                    ulonglong2 wb = *(const ulonglong2*)(wrow + k * 4 + 2);
                    #pragma unroll
                    for (int j = 0; j < 4; j++) {
                        acc[0][j] = ffma2(wa.x, tv[dc + j], acc[0][j]);
                        acc[1][j] = ffma2(wa.y, tv[dc + j], acc[1][j]);
                        acc[2][j] = ffma2(wb.x, tv[dc + j], acc[2][j]);
                        acc[3][j] = ffma2(wb.y, tv[dc + j], acc[3][j]);
                    }
                }
            }
        }
        if (ci < C2 - 1) {
            const int nxt = cur ^ 1;
            #pragma unroll
            for (int s = 0; s < 4; s++)
                if (si[s] >= 0) tile[nxt][si[s]] = v[s];
        }
        __syncthreads();
    }

    if (tid < 196) {
        #pragma unroll
        for (int c = 0; c < 4; c++) {
            float2 v0 = unpack2(acc[c][0]), v1 = unpack2(acc[c][1]);
            float2 v2 = unpack2(acc[c][2]), v3 = unpack2(acc[c][3]);
            int co = cog * 8 + 2 * c;
            float4 oa = { v0.x, v1.x, v2.x, v3.x };
            float4 ob = { v0.y, v1.y, v2.y, v3.y };
            *(float4*)(out + (n * C3 + co) * HW + p0) = oa;
            *(float4*)(out + (n * C3 + co + 1) * HW + p0) = ob;
        }
    }
}

// ---------------- launch ----------------
extern "C" void kernel_launch(void* const* d_in, const int* in_sizes, int n_in,
                              void* d_out, int out_size) {
    const float* x  = (const float*)d_in[0];
    const float* g1 = (const float*)d_in[1];
    const float* b1 = (const float*)d_in[2];
    const float* m1 = (const float*)d_in[3];
    const float* v1 = (const float*)d_in[4];
    const float* w1 = (const float*)d_in[5];
    const float* g2 = (const float*)d_in[6];
    const float* b2 = (const float*)d_in[7];
    const float* m2 = (const float*)d_in[8];
    const float* v2 = (const float*)d_in[9];
    const float* w2 = (const float*)d_in[10];
    float* out = (float*)d_out;

    prep_k<<<1, 512>>>(g1, b1, m1, v1, g2, b2, m2, v2);
    wquant_k<<<2, 256>>>(w1, w2);
    h1mm_k<<<2048, 256>>>(x);
    conv1_k<<<NPIX / 64, 256>>>(x);
    h2q_k<<<(Nn * C2 * HW / 4 + 255) / 256, 256>>>();
    conv2_k<<<dim3(4, Nn), 256>>>(out);
}

// round 5
// speedup vs baseline: 3.0258x; 1.3784x over previous
#include <cuda_runtime.h>

typedef unsigned long long ull;
typedef unsigned char u8;

#define Nn 64
#define C1 512
#define C2 128
#define C3 32
#define HW 784
#define NPIX (Nn*HW)   // 50176

#define FMAXV 3.402823466e38f

// ---------------- device scratch ----------------
__device__ float g_a1[C1], g_b1v[C1], g_a2[C2], g_b2v[C2];
__device__ uint4 g_w1p[8*16*32];                // w1 u8 codes, mma-fragment-permuted
__device__ float g_j1row[C2];                   // per-co sum of w1 codes
__device__ float g_w1mn, g_w1s;                 // w1 quant params
__device__ float g_w2mn, g_w2s;                 // w2 quant params
__device__ uint4 g_w2p[2304];                   // w2 codes fragment-packed [(tap*4+g)*2+mtile][lane]
__device__ float g_Jtap[C3*9];                  // per-(co,tap) code sums
__device__ float g_Jall[C3];                    // per-co total code sums
__device__ __align__(16) float g_h2buf[NPIX*C2];   // h2 pre-quant, [pixel][co] layout
__device__ __align__(16) u8    g_h2q[NPIX*C2];     // h2 u8 codes, [pixel][ci] layout
__device__ float g_T[NPIX];                        // per-pixel sum of codes
__device__ unsigned g_h1mn, g_h1mx, g_h2mn, g_h2mx;

// ---------------- helpers ----------------
__device__ __forceinline__ void mma_u8(int* d, unsigned a0, unsigned a1, unsigned a2, unsigned a3,
                                       unsigned b0, unsigned b1) {
    asm volatile("mma.sync.aligned.m16n8k32.row.col.s32.u8.u8.s32 "
                 "{%0,%1,%2,%3},{%4,%5,%6,%7},{%8,%9},{%0,%1,%2,%3};"
                 : "+r"(d[0]), "+r"(d[1]), "+r"(d[2]), "+r"(d[3])
                 : "r"(a0), "r"(a1), "r"(a2), "r"(a3), "r"(b0), "r"(b1));
}
__device__ __forceinline__ float wredmin(float v) {
    #pragma unroll
    for (int o = 16; o > 0; o >>= 1) v = fminf(v, __shfl_xor_sync(0xffffffffu, v, o));
    return v;
}
__device__ __forceinline__ float wredmax(float v) {
    #pragma unroll
    for (int o = 16; o > 0; o >>= 1) v = fmaxf(v, __shfl_xor_sync(0xffffffffu, v, o));
    return v;
}

// ---------------- 1: prep ----------------
__global__ void prep_k(const float* __restrict__ g1, const float* __restrict__ b1,
                       const float* __restrict__ m1, const float* __restrict__ v1,
                       const float* __restrict__ g2, const float* __restrict__ b2,
                       const float* __restrict__ m2, const float* __restrict__ v2) {
    int t = threadIdx.x;
    if (t == 0) { g_h1mn = 0x7f7fffffu; g_h1mx = 0u; g_h2mn = 0x7f7fffffu; g_h2mx = 0u; }
    if (t < C1) {
        float inv = g1[t] / sqrtf(v1[t] + 1e-5f);
        g_a1[t] = inv; g_b1v[t] = b1[t] - m1[t] * inv;
    }
    if (t < C2) {
        float inv = g2[t] / sqrtf(v2[t] + 1e-5f);
        g_a2[t] = inv; g_b2v[t] = b2[t] - m2[t] * inv;
    }
}

// ---------------- 2: weight fake-quant ----------------
// block 0: w1 -> u8 fragment codes + Jrow; block 1: w2 -> u8 fragment codes + Jtap/Jall
__global__ void wquant_k(const float* __restrict__ w1, const float* __restrict__ w2) {
    __shared__ float smn[256], smx[256];
    __shared__ u8 s_code[C3*C2*9];   // 36864 B (block 1 only)
    int which = blockIdx.x, t = threadIdx.x;
    const float* w = which ? w2 : w1;
    int n = which ? C3 * C2 * 9 : C2 * C1;
    float mn = FMAXV, mx = -FMAXV;
    for (int i = t; i < n; i += 256) { float v = w[i]; mn = fminf(mn, v); mx = fmaxf(mx, v); }
    smn[t] = mn; smx[t] = mx; __syncthreads();
    for (int s = 128; s > 0; s >>= 1) {
        if (t < s) { smn[t] = fminf(smn[t], smn[t + s]); smx[t] = fmaxf(smx[t], smx[t + s]); }
        __syncthreads();
    }
    float mnv = smn[0];
    float sc = fmaxf((smx[0] - mnv) * (1.f / 255.f), 1e-8f);
    if (which == 0) {
        if (t == 0) { g_w1mn = mnv; g_w1s = sc; }
        for (int f = t; f < 8 * 16 * 32; f += 256) {
            int m = f >> 9;
            int rem = f & 511;
            int q = rem >> 5, L = rem & 31;
            unsigned rg[4];
            #pragma unroll
            for (int r = 0; r < 4; r++) {
                int row = m * 16 + (L >> 2) + (r & 1) * 8;
                int kc = q * 32 + (r >> 1) * 16 + (L & 3) * 4;
                unsigned u = 0;
                #pragma unroll
                for (int i = 0; i < 4; i++) {
                    int code = __float2int_rn(__fdiv_rn(w1[row * C1 + kc + i] - mnv, sc));
                    u |= ((unsigned)code & 0xffu) << (8 * i);
                }
                rg[r] = u;
            }
            g_w1p[f] = make_uint4(rg[0], rg[1], rg[2], rg[3]);
        }
        if (t < C2) {
            int s = 0;
            for (int ci = 0; ci < C1; ci++)
                s += __float2int_rn(__fdiv_rn(w1[t * C1 + ci] - mnv, sc));
            g_j1row[t] = (float)s;
        }
    } else {
        if (t == 0) { g_w2mn = mnv; g_w2s = sc; }
        // codes into smem: layout (co*128+ci)*9+tap matches w2 [co][ci][3][3]
        for (int i = t; i < n; i += 256)
            s_code[i] = (u8)__float2int_rn(__fdiv_rn(w2[i] - mnv, sc));
        __syncthreads();
        // Jtap
        for (int e = t; e < C3 * 9; e += 256) {
            int co = e / 9, tap = e - co * 9;
            int s = 0;
            for (int ci = 0; ci < C2; ci++) s += s_code[(co * C2 + ci) * 9 + tap];
            g_Jtap[e] = (float)s;
        }
        // Jall
        if (t < C3) {
            int s = 0;
            for (int i = 0; i < C2 * 9; i++) s += s_code[t * C2 * 9 + i];
            g_Jall[t] = (float)s;
        }
        // fragment pack: f = ((tap*4+g)*2+mtile)*32+lane
        for (int f = t; f < 2304; f += 256) {
            int lane = f & 31;
            int u = f >> 5;
            int mtile = u & 1;
            int v2i = u >> 1;
            int g = v2i & 3, tap = v2i >> 2;
            int co_b = mtile * 16 + (lane >> 2);
            int ci_b = g * 32 + (lane & 3) * 4;
            unsigned rg[4];
            #pragma unroll
            for (int r = 0; r < 4; r++) {
                int co = co_b + (r & 1) * 8;
                int ci0 = ci_b + (r >> 1) * 16;
                unsigned uu = 0;
                #pragma unroll
                for (int i = 0; i < 4; i++)
                    uu |= ((unsigned)s_code[(co * C2 + ci0 + i) * 9 + tap]) << (8 * i);
                rg[r] = uu;
            }
            g_w2p[f] = make_uint4(rg[0], rg[1], rg[2], rg[3]);
        }
    }
}

// ---------------- 3: global min/max of relu(BN1(x)) ----------------
__global__ void h1mm_k(const float* __restrict__ x) {
    const int NV = Nn * C1 * HW / 4;
    float mn = FMAXV, mx = 0.f;
    for (int v = blockIdx.x * blockDim.x + threadIdx.x; v < NV; v += gridDim.x * blockDim.x) {
        int ci = (v / 196) & 511;
        float4 p = ((const float4*)x)[v];
        float a = g_a1[ci], b = g_b1v[ci];
        float h0 = fmaxf(fmaf(a, p.x, b), 0.f);
        float h1 = fmaxf(fmaf(a, p.y, b), 0.f);
        float h2 = fmaxf(fmaf(a, p.z, b), 0.f);
        float h3 = fmaxf(fmaf(a, p.w, b), 0.f);
        mn = fminf(mn, fminf(fminf(h0, h1), fminf(h2, h3)));
        mx = fmaxf(mx, fmaxf(fmaxf(h0, h1), fmaxf(h2, h3)));
    }
    __shared__ float smn[8], smx[8];
    float bm = wredmin(mn), bM = wredmax(mx);
    int w = threadIdx.x >> 5, ln = threadIdx.x & 31;
    if (ln == 0) { smn[w] = bm; smx[w] = bM; }
    __syncthreads();
    if (w == 0) {
        float m2 = (ln < 8) ? smn[ln] : FMAXV;
        float M2 = (ln < 8) ? smx[ln] : 0.f;
        m2 = wredmin(m2); M2 = wredmax(M2);
        if (ln == 0) {
            atomicMin(&g_h1mn, __float_as_uint(m2));
            atomicMax(&g_h1mx, __float_as_uint(M2));
        }
    }
}

// ---------------- 4: conv1x1 via u8 IMMA ----------------
#define BPITCH 80
__global__ __launch_bounds__(256) void conv1_k(const float* __restrict__ x) {
    __shared__ __align__(16) u8 Bs[64 * BPITCH];
    __shared__ int kcp[4][64];
    __shared__ float kcolF[64];
    __shared__ float sa1[C1], sb1[C1];
    __shared__ float smn[8], smx[8];

    const int tid = threadIdx.x;
    const int lane = tid & 31, wid = tid >> 5;
    const int col0 = blockIdx.x * 64;

    #pragma unroll
    for (int l = 0; l < 2; l++) {
        int e = tid + l * 256;
        sa1[e] = g_a1[e]; sb1[e] = g_b1v[e];
    }

    const float mn1 = __uint_as_float(g_h1mn);
    const float mx1 = __uint_as_float(g_h1mx);
    const float s1 = fmaxf((mx1 - mn1) * (1.f / 255.f), 1e-8f);
    const float i1 = 1.f / s1;

    const int pB = tid & 63;
    const int tq = tid >> 6;
    const int gpB = col0 + pB;
    const int nimgB = gpB / 784;
    const float* xb = x + nimgB * C1 * HW + (gpB - nimgB * 784);

    int acc[8][4];
    #pragma unroll
    for (int t = 0; t < 8; t++)
        #pragma unroll
        for (int r = 0; r < 4; r++) acc[t][r] = 0;

    float v[16];
    #pragma unroll
    for (int i = 0; i < 16; i++) {
        int ci = ((i >> 2) * 4 + tq) * 4 + (i & 3);
        v[i] = xb[ci * HW];
    }
    int ksum = 0;
    __syncthreads();

    for (int c = 0; c < 8; c++) {
        #pragma unroll
        for (int s = 0; s < 4; s++) {
            unsigned u = 0;
            #pragma unroll
            for (int j = 0; j < 4; j++) {
                int ci = c * 64 + (s * 4 + tq) * 4 + j;
                float h = fmaxf(fmaf(sa1[ci], v[s * 4 + j], sb1[ci]), 0.f);
                int code = __float2int_rn((h - mn1) * i1);
                ksum += code;
                u |= ((unsigned)code & 0xffu) << (8 * j);
            }
            *(unsigned*)(Bs + pB * BPITCH + (s * 4 + tq) * 4) = u;
        }
        __syncthreads();
        if (c < 7) {
            #pragma unroll
            for (int i = 0; i < 16; i++) {
                int ci = (c + 1) * 64 + ((i >> 2) * 4 + tq) * 4 + (i & 3);
                v[i] = xb[ci * HW];
            }
        }
        #pragma unroll
        for (int q2 = 0; q2 < 2; q2++) {
            int q = c * 2 + q2;
            uint4 a = g_w1p[(wid * 16 + q) * 32 + lane];
            const u8* bbase = Bs + (lane >> 2) * BPITCH + q2 * 32 + (lane & 3) * 4;
            #pragma unroll
            for (int t = 0; t < 8; t++) {
                unsigned b0 = *(const unsigned*)(bbase + t * 8 * BPITCH);
                unsigned b1 = *(const unsigned*)(bbase + t * 8 * BPITCH + 16);
                mma_u8(acc[t], a.x, a.y, a.z, a.w, b0, b1);
            }
        }
        __syncthreads();
    }

    kcp[tq][pB] = ksum;
    __syncthreads();
    if (tid < 64) kcolF[tid] = (float)(kcp[0][tid] + kcp[1][tid] + kcp[2][tid] + kcp[3][tid]);
    __syncthreads();

    const float sw = g_w1s, mnw = g_w1mn;
    const float cS = sw * s1;
    const float cK = mnw * s1;
    const float cJ = sw * mn1;
    const float cD = 512.f * mnw * mn1;

    const int g = lane >> 2;
    const int co0 = wid * 16 + g, co1 = co0 + 8;
    const float base0 = fmaf(cJ, g_j1row[co0], cD);
    const float base1 = fmaf(cJ, g_j1row[co1], cD);
    const float a20 = g_a2[co0], b20 = g_b2v[co0];
    const float a21 = g_a2[co1], b21 = g_b2v[co1];

    float lmn = FMAXV, lmx = 0.f;
    #pragma unroll
    for (int t = 0; t < 8; t++) {
        int pl = t * 8 + (lane & 3) * 2;
        float kc0 = kcolF[pl], kc1 = kcolF[pl + 1];
        float y00 = fmaf(cS, __int2float_rn(acc[t][0]), fmaf(cK, kc0, base0));
        float y01 = fmaf(cS, __int2float_rn(acc[t][1]), fmaf(cK, kc1, base0));
        float y10 = fmaf(cS, __int2float_rn(acc[t][2]), fmaf(cK, kc0, base1));
        float y11 = fmaf(cS, __int2float_rn(acc[t][3]), fmaf(cK, kc1, base1));
        float h00 = fmaxf(fmaf(a20, y00, b20), 0.f);
        float h01 = fmaxf(fmaf(a20, y01, b20), 0.f);
        float h10 = fmaxf(fmaf(a21, y10, b21), 0.f);
        float h11 = fmaxf(fmaf(a21, y11, b21), 0.f);
        lmn = fminf(lmn, fminf(fminf(h00, h01), fminf(h10, h11)));
        lmx = fmaxf(lmx, fmaxf(fmaxf(h00, h01), fmaxf(h10, h11)));
        int px0 = col0 + pl;
        // [pixel][channel] layout
        g_h2buf[px0 * C2 + co0]       = h00;
        g_h2buf[(px0 + 1) * C2 + co0] = h01;
        g_h2buf[px0 * C2 + co1]       = h10;
        g_h2buf[(px0 + 1) * C2 + co1] = h11;
    }
    float bm = wredmin(lmn), bM = wredmax(lmx);
    if (lane == 0) { smn[wid] = bm; smx[wid] = bM; }
    __syncthreads();
    if (wid == 0) {
        float m2 = (lane < 8) ? smn[lane] : FMAXV;
        float M2 = (lane < 8) ? smx[lane] : 0.f;
        m2 = wredmin(m2); M2 = wredmax(M2);
        if (lane == 0) {
            atomicMin(&g_h2mn, __float_as_uint(m2));
            atomicMax(&g_h2mx, __float_as_uint(M2));
        }
    }
}

// ---------------- 4.5: h2 -> u8 codes + per-pixel code sums ----------------
__global__ __launch_bounds__(256) void codes_k() {
    int gp = blockIdx.x * 256 + threadIdx.x;   // pixel id, 50176 total
    const float mn = __uint_as_float(g_h2mn);
    const float mx = __uint_as_float(g_h2mx);
    const float s = fmaxf((mx - mn) * (1.f / 255.f), 1e-8f);
    const float inv = 1.f / s;
    const float4* src = (const float4*)(g_h2buf + (size_t)gp * C2);
    uint4* dst = (uint4*)(g_h2q + (size_t)gp * C2);
    int ksum = 0;
    #pragma unroll
    for (int b = 0; b < 8; b++) {
        unsigned wds[4];
        #pragma unroll
        for (int j = 0; j < 4; j++) {
            float4 v = src[b * 4 + j];
            int c0 = __float2int_rn((v.x - mn) * inv);
            int c1 = __float2int_rn((v.y - mn) * inv);
            int c2 = __float2int_rn((v.z - mn) * inv);
            int c3 = __float2int_rn((v.w - mn) * inv);
            ksum += c0 + c1 + c2 + c3;
            wds[j] = (unsigned)c0 | ((unsigned)c1 << 8) | ((unsigned)c2 << 16) | ((unsigned)c3 << 24);
        }
        dst[b] = make_uint4(wds[0], wds[1], wds[2], wds[3]);
    }
    g_T[gp] = (float)ksum;
}

// ---------------- 5: conv3x3 via u8 IMMA ----------------
// block = (slice of 2 rows, image); 7 warps each do one n8 pixel tile, warp 7 idle in mma.
__global__ __launch_bounds__(256) void conv2_k(float* __restrict__ out) {
    __shared__ uint4 s_w[2304];          // 36.9 KB
    __shared__ float s_T[4 * 28];
    __shared__ float s_K9[56];
    __shared__ float s_Jtap[C3 * 9];
    __shared__ float s_Jall[C3];

    const int tid = threadIdx.x;
    const int lane = tid & 31, wid = tid >> 5;
    const int n = blockIdx.y, sl = blockIdx.x;
    const int r0 = sl * 2;

    for (int f = tid; f < 2304; f += 256) s_w[f] = g_w2p[f];
    for (int e = tid; e < 112; e += 256) {
        int rr = r0 - 1 + e / 28, cc = e - (e / 28) * 28;
        s_T[e] = ((unsigned)rr < 28u) ? g_T[n * 784 + rr * 28 + cc] : 0.f;
    }
    for (int e = tid; e < C3 * 9; e += 256) s_Jtap[e] = g_Jtap[e];
    if (tid < C3) s_Jall[tid] = g_Jall[tid];
    __syncthreads();
    if (tid < 56) {
        int rl = tid / 28, c = tid - rl * 28;
        float s = 0.f;
        #pragma unroll
        for (int dr = 0; dr < 3; dr++) {
            #pragma unroll
            for (int dc = -1; dc <= 1; dc++) {
                int cc = c + dc;
                if ((unsigned)cc < 28u) s += s_T[(rl + dr) * 28 + cc];
            }
        }
        s_K9[tid] = s;
    }
    __syncthreads();

    if (wid >= 7) return;

    // B-load pixel for this lane
    const int ql = wid * 8 + (lane >> 2);
    const int rp = r0 + ql / 28, cp = ql - (ql / 28) * 28;
    const u8* bp = g_h2q + ((size_t)(n * 784 + rp * 28 + cp)) * C2 + (lane & 3) * 4;

    int acc0[4] = {0, 0, 0, 0}, acc1[4] = {0, 0, 0, 0};

    #pragma unroll
    for (int t = 0; t < 9; t++) {
        const int dr = t / 3 - 1, dc = t % 3 - 1;
        const bool valid = ((unsigned)(rp + dr) < 28u) && ((unsigned)(cp + dc) < 28u);
        const u8* bt = bp + (dr * 28 + dc) * C2;
        #pragma unroll
        for (int g = 0; g < 4; g++) {
            unsigned b0 = 0, b1 = 0;
            if (valid) {
                b0 = *(const unsigned*)(bt + g * 32);
                b1 = *(const unsigned*)(bt + g * 32 + 16);
            }
            uint4 a0 = s_w[((t * 4 + g) * 2 + 0) * 32 + lane];
            mma_u8(acc0, a0.x, a0.y, a0.z, a0.w, b0, b1);
            uint4 a1 = s_w[((t * 4 + g) * 2 + 1) * 32 + lane];
            mma_u8(acc1, a1.x, a1.y, a1.z, a1.w, b0, b1);
        }
    }

    // epilogue
    const float mn2 = __uint_as_float(g_h2mn);
    const float mx2 = __uint_as_float(g_h2mx);
    const float s2 = fmaxf((mx2 - mn2) * (1.f / 255.f), 1e-8f);
    const float sw = g_w2s, mnw = g_w2mn;
    const float cS = sw * s2;
    const float cK = mnw * s2;
    const float cJ = sw * mn2;
    const float cD = 1152.f * mnw * mn2;

    const int qa = wid * 8 + 2 * (lane & 3);   // even, so qa+1 in same block-slice
    const int co_r = lane >> 2;

    #pragma unroll
    for (int e = 0; e < 2; e++) {
        const int q = qa + e;
        const float k9 = s_K9[q];
        const int r = r0 + q / 28, c = q - (q / 28) * 28;
        const bool border = (r == 0) | (r == 27) | (c == 0) | (c == 27);
        // padded-tap mask data
        int npad = 0;
        float sj[4] = {0.f, 0.f, 0.f, 0.f};
        if (border) {
            #pragma unroll
            for (int t = 0; t < 9; t++) {
                const int dr = t / 3 - 1, dc = t % 3 - 1;
                const bool pad = ((unsigned)(r + dr) >= 28u) || ((unsigned)(c + dc) >= 28u);
                if (pad) {
                    npad++;
                    #pragma unroll
                    for (int m = 0; m < 4; m++) sj[m] += s_Jtap[(co_r + 8 * m) * 9 + t];
                }
            }
        }
        #pragma unroll
        for (int m = 0; m < 4; m++) {
            const int co = co_r + 8 * m;
            int S = (m == 0) ? acc0[0 + e] : (m == 1) ? acc0[2 + e] : (m == 2) ? acc1[0 + e] : acc1[2 + e];
            float y = fmaf(cS, __int2float_rn(S), fmaf(cK, k9, fmaf(cJ, s_Jall[co], cD)));
            if (border) y -= mn2 * fmaf(sw, sj[m], mnw * 128.f * (float)npad);
            out[(n * C3 + co) * HW + r * 28 + c] = y;
        }
    }
}

// ---------------- launch ----------------
extern "C" void kernel_launch(void* const* d_in, const int* in_sizes, int n_in,
                              void* d_out, int out_size) {
    const float* x  = (const float*)d_in[0];
    const float* g1 = (const float*)d_in[1];
    const float* b1 = (const float*)d_in[2];
    const float* m1 = (const float*)d_in[3];
    const float* v1 = (const float*)d_in[4];
    const float* w1 = (const float*)d_in[5];
    const float* g2 = (const float*)d_in[6];
    const float* b2 = (const float*)d_in[7];
    const float* m2 = (const float*)d_in[8];
    const float* v2 = (const float*)d_in[9];
    const float* w2 = (const float*)d_in[10];
    float* out = (float*)d_out;

    prep_k<<<1, 512>>>(g1, b1, m1, v1, g2, b2, m2, v2);
    wquant_k<<<2, 256>>>(w1, w2);
    h1mm_k<<<2048, 256>>>(x);
    conv1_k<<<NPIX / 64, 256>>>(x);
    codes_k<<<NPIX / 256, 256>>>();
    conv2_k<<<dim3(14, Nn), 256>>>(out);
}

// round 6
// speedup vs baseline: 3.0562x; 1.0100x over previous
#include <cuda_runtime.h>

typedef unsigned long long ull;
typedef unsigned char u8;

#define Nn 64
#define C1 512
#define C2 128
#define C3 32
#define HW 784
#define NPIX (Nn*HW)   // 50176

#define FMAXV 3.402823466e38f

// ---------------- device scratch ----------------
__device__ float g_a1[C1], g_b1v[C1], g_a2[C2], g_b2v[C2];
__device__ uint4 g_w1p[8*16*32];                // w1 u8 codes, mma-fragment-permuted
__device__ float g_j1row[C2];                   // per-co sum of w1 codes
__device__ float g_w1mn, g_w1s;                 // w1 quant params
__device__ float g_w2mn, g_w2s;                 // w2 quant params
__device__ uint4 g_w2p[2304];                   // w2 codes fragment-packed [(tap*4+g)*2+mtile][lane]
__device__ float g_Jtap[C3*9];                  // per-(co,tap) code sums
__device__ float g_Jall[C3];                    // per-co total code sums
__device__ __align__(16) float g_h2buf[NPIX*C2];   // h2 pre-quant, [pixel][co] layout
__device__ __align__(16) u8    g_h2q[NPIX*C2];     // h2 u8 codes, [pixel][ci] layout
__device__ float g_T[NPIX];                        // per-pixel sum of codes
__device__ unsigned g_h1mn, g_h1mx, g_h2mn, g_h2mx;

// ---------------- helpers ----------------
__device__ __forceinline__ void mma_u8(int* d, unsigned a0, unsigned a1, unsigned a2, unsigned a3,
                                       unsigned b0, unsigned b1) {
    asm volatile("mma.sync.aligned.m16n8k32.row.col.s32.u8.u8.s32 "
                 "{%0,%1,%2,%3},{%4,%5,%6,%7},{%8,%9},{%0,%1,%2,%3};"
                 : "+r"(d[0]), "+r"(d[1]), "+r"(d[2]), "+r"(d[3])
                 : "r"(a0), "r"(a1), "r"(a2), "r"(a3), "r"(b0), "r"(b1));
}
__device__ __forceinline__ float wredmin(float v) {
    #pragma unroll
    for (int o = 16; o > 0; o >>= 1) v = fminf(v, __shfl_xor_sync(0xffffffffu, v, o));
    return v;
}
__device__ __forceinline__ float wredmax(float v) {
    #pragma unroll
    for (int o = 16; o > 0; o >>= 1) v = fmaxf(v, __shfl_xor_sync(0xffffffffu, v, o));
    return v;
}

// ---------------- 1: prep ----------------
__global__ void prep_k(const float* __restrict__ g1, const float* __restrict__ b1,
                       const float* __restrict__ m1, const float* __restrict__ v1,
                       const float* __restrict__ g2, const float* __restrict__ b2,
                       const float* __restrict__ m2, const float* __restrict__ v2) {
    int t = threadIdx.x;
    if (t == 0) { g_h1mn = 0x7f7fffffu; g_h1mx = 0u; g_h2mn = 0x7f7fffffu; g_h2mx = 0u; }
    if (t < C1) {
        float inv = g1[t] / sqrtf(v1[t] + 1e-5f);
        g_a1[t] = inv; g_b1v[t] = b1[t] - m1[t] * inv;
    }
    if (t < C2) {
        float inv = g2[t] / sqrtf(v2[t] + 1e-5f);
        g_a2[t] = inv; g_b2v[t] = b2[t] - m2[t] * inv;
    }
}

// ---------------- 2: weight fake-quant ----------------
__global__ void wquant_k(const float* __restrict__ w1, const float* __restrict__ w2) {
    __shared__ float smn[256], smx[256];
    __shared__ u8 s_code[C3*C2*9];   // block 1 only
    int which = blockIdx.x, t = threadIdx.x;
    const float* w = which ? w2 : w1;
    int n = which ? C3 * C2 * 9 : C2 * C1;
    float mn = FMAXV, mx = -FMAXV;
    for (int i = t; i < n; i += 256) { float v = w[i]; mn = fminf(mn, v); mx = fmaxf(mx, v); }
    smn[t] = mn; smx[t] = mx; __syncthreads();
    for (int s = 128; s > 0; s >>= 1) {
        if (t < s) { smn[t] = fminf(smn[t], smn[t + s]); smx[t] = fmaxf(smx[t], smx[t + s]); }
        __syncthreads();
    }
    float mnv = smn[0];
    float sc = fmaxf((smx[0] - mnv) * (1.f / 255.f), 1e-8f);
    if (which == 0) {
        if (t == 0) { g_w1mn = mnv; g_w1s = sc; }
        for (int f = t; f < 8 * 16 * 32; f += 256) {
            int m = f >> 9;
            int rem = f & 511;
            int q = rem >> 5, L = rem & 31;
            unsigned rg[4];
            #pragma unroll
            for (int r = 0; r < 4; r++) {
                int row = m * 16 + (L >> 2) + (r & 1) * 8;
                int kc = q * 32 + (r >> 1) * 16 + (L & 3) * 4;
                unsigned u = 0;
                #pragma unroll
                for (int i = 0; i < 4; i++) {
                    int code = __float2int_rn(__fdiv_rn(w1[row * C1 + kc + i] - mnv, sc));
                    u |= ((unsigned)code & 0xffu) << (8 * i);
                }
                rg[r] = u;
            }
            g_w1p[f] = make_uint4(rg[0], rg[1], rg[2], rg[3]);
        }
        if (t < C2) {
            int s = 0;
            for (int ci = 0; ci < C1; ci++)
                s += __float2int_rn(__fdiv_rn(w1[t * C1 + ci] - mnv, sc));
            g_j1row[t] = (float)s;
        }
    } else {
        if (t == 0) { g_w2mn = mnv; g_w2s = sc; }
        for (int i = t; i < n; i += 256)
            s_code[i] = (u8)__float2int_rn(__fdiv_rn(w2[i] - mnv, sc));
        __syncthreads();
        for (int e = t; e < C3 * 9; e += 256) {
            int co = e / 9, tap = e - co * 9;
            int s = 0;
            for (int ci = 0; ci < C2; ci++) s += s_code[(co * C2 + ci) * 9 + tap];
            g_Jtap[e] = (float)s;
        }
        if (t < C3) {
            int s = 0;
            for (int i = 0; i < C2 * 9; i++) s += s_code[t * C2 * 9 + i];
            g_Jall[t] = (float)s;
        }
        for (int f = t; f < 2304; f += 256) {
            int lane = f & 31;
            int u = f >> 5;
            int mtile = u & 1;
            int v2i = u >> 1;
            int g = v2i & 3, tap = v2i >> 2;
            int co_b = mtile * 16 + (lane >> 2);
            int ci_b = g * 32 + (lane & 3) * 4;
            unsigned rg[4];
            #pragma unroll
            for (int r = 0; r < 4; r++) {
                int co = co_b + (r & 1) * 8;
                int ci0 = ci_b + (r >> 1) * 16;
                unsigned uu = 0;
                #pragma unroll
                for (int i = 0; i < 4; i++)
                    uu |= ((unsigned)s_code[(co * C2 + ci0 + i) * 9 + tap]) << (8 * i);
                rg[r] = uu;
            }
            g_w2p[f] = make_uint4(rg[0], rg[1], rg[2], rg[3]);
        }
    }
}

// ---------------- 3: global min/max of relu(BN1(x)) ----------------
__global__ void h1mm_k(const float* __restrict__ x) {
    const int NV = Nn * C1 * HW / 4;
    float mn = FMAXV, mx = 0.f;
    for (int v = blockIdx.x * blockDim.x + threadIdx.x; v < NV; v += gridDim.x * blockDim.x) {
        int ci = (v / 196) & 511;
        float4 p = ((const float4*)x)[v];
        float a = g_a1[ci], b = g_b1v[ci];
        float h0 = fmaxf(fmaf(a, p.x, b), 0.f);
        float h1 = fmaxf(fmaf(a, p.y, b), 0.f);
        float h2 = fmaxf(fmaf(a, p.z, b), 0.f);
        float h3 = fmaxf(fmaf(a, p.w, b), 0.f);
        mn = fminf(mn, fminf(fminf(h0, h1), fminf(h2, h3)));
        mx = fmaxf(mx, fmaxf(fmaxf(h0, h1), fmaxf(h2, h3)));
    }
    __shared__ float smn[8], smx[8];
    float bm = wredmin(mn), bM = wredmax(mx);
    int w = threadIdx.x >> 5, ln = threadIdx.x & 31;
    if (ln == 0) { smn[w] = bm; smx[w] = bM; }
    __syncthreads();
    if (w == 0) {
        float m2 = (ln < 8) ? smn[ln] : FMAXV;
        float M2 = (ln < 8) ? smx[ln] : 0.f;
        m2 = wredmin(m2); M2 = wredmax(M2);
        if (ln == 0) {
            atomicMin(&g_h1mn, __float_as_uint(m2));
            atomicMax(&g_h1mx, __float_as_uint(M2));
        }
    }
}

// ---------------- 4: conv1x1 via u8 IMMA, double-buffered B ----------------
#define BPITCH 80
#define BUFSZ (64*BPITCH)
__global__ __launch_bounds__(256) void conv1_k(const float* __restrict__ x) {
    __shared__ __align__(16) u8 Bs[2 * BUFSZ];
    __shared__ int kcp[4][64];
    __shared__ float kcolF[64];
    __shared__ float sa1[C1], sb1[C1];
    __shared__ float smn[8], smx[8];

    const int tid = threadIdx.x;
    const int lane = tid & 31, wid = tid >> 5;
    const int col0 = blockIdx.x * 64;

    #pragma unroll
    for (int l = 0; l < 2; l++) {
        int e = tid + l * 256;
        sa1[e] = g_a1[e]; sb1[e] = g_b1v[e];
    }

    const float mn1 = __uint_as_float(g_h1mn);
    const float mx1 = __uint_as_float(g_h1mx);
    const float s1 = fmaxf((mx1 - mn1) * (1.f / 255.f), 1e-8f);
    const float i1 = 1.f / s1;

    const int pB = tid & 63;
    const int tq = tid >> 6;
    const int gpB = col0 + pB;
    const int nimgB = gpB / 784;
    const float* xb = x + nimgB * C1 * HW + (gpB - nimgB * 784);

    int acc[8][4];
    #pragma unroll
    for (int t = 0; t < 8; t++)
        #pragma unroll
        for (int r = 0; r < 4; r++) acc[t][r] = 0;

    float v[16];
    #pragma unroll
    for (int i = 0; i < 16; i++) {
        int ci = ((i >> 2) * 4 + tq) * 4 + (i & 3);
        v[i] = xb[ci * HW];
    }
    int ksum = 0;
    __syncthreads();   // sa1/sb1 ready

    // produce chunk 0 into buffer 0
    #pragma unroll
    for (int s = 0; s < 4; s++) {
        unsigned u = 0;
        #pragma unroll
        for (int j = 0; j < 4; j++) {
            int ci = (s * 4 + tq) * 4 + j;
            float h = fmaxf(fmaf(sa1[ci], v[s * 4 + j], sb1[ci]), 0.f);
            int code = __float2int_rn((h - mn1) * i1);
            ksum += code;
            u |= ((unsigned)code & 0xffu) << (8 * j);
        }
        *(unsigned*)(Bs + pB * BPITCH + (s * 4 + tq) * 4) = u;
    }
    // prefetch chunk 1
    #pragma unroll
    for (int i = 0; i < 16; i++) {
        int ci = 64 + ((i >> 2) * 4 + tq) * 4 + (i & 3);
        v[i] = xb[ci * HW];
    }
    __syncthreads();

    for (int c = 0; c < 8; c++) {
        const u8* curB = Bs + (c & 1) * BUFSZ;
        if (c < 7) {
            u8* nxtB = Bs + ((c + 1) & 1) * BUFSZ;
            #pragma unroll
            for (int s = 0; s < 4; s++) {
                unsigned u = 0;
                #pragma unroll
                for (int j = 0; j < 4; j++) {
                    int ci = (c + 1) * 64 + (s * 4 + tq) * 4 + j;
                    float h = fmaxf(fmaf(sa1[ci], v[s * 4 + j], sb1[ci]), 0.f);
                    int code = __float2int_rn((h - mn1) * i1);
                    ksum += code;
                    u |= ((unsigned)code & 0xffu) << (8 * j);
                }
                *(unsigned*)(nxtB + pB * BPITCH + (s * 4 + tq) * 4) = u;
            }
            if (c < 6) {
                #pragma unroll
                for (int i = 0; i < 16; i++) {
                    int ci = (c + 2) * 64 + ((i >> 2) * 4 + tq) * 4 + (i & 3);
                    v[i] = xb[ci * HW];
                }
            }
        }
        #pragma unroll
        for (int q2 = 0; q2 < 2; q2++) {
            int q = c * 2 + q2;
            uint4 a = g_w1p[(wid * 16 + q) * 32 + lane];
            const u8* bbase = curB + (lane >> 2) * BPITCH + q2 * 32 + (lane & 3) * 4;
            #pragma unroll
            for (int t = 0; t < 8; t++) {
                unsigned b0 = *(const unsigned*)(bbase + t * 8 * BPITCH);
                unsigned b1 = *(const unsigned*)(bbase + t * 8 * BPITCH + 16);
                mma_u8(acc[t], a.x, a.y, a.z, a.w, b0, b1);
            }
        }
        __syncthreads();
    }

    kcp[tq][pB] = ksum;
    __syncthreads();
    if (tid < 64) kcolF[tid] = (float)(kcp[0][tid] + kcp[1][tid] + kcp[2][tid] + kcp[3][tid]);
    __syncthreads();

    const float sw = g_w1s, mnw = g_w1mn;
    const float cS = sw * s1;
    const float cK = mnw * s1;
    const float cJ = sw * mn1;
    const float cD = 512.f * mnw * mn1;

    const int g = lane >> 2;
    const int co0 = wid * 16 + g, co1 = co0 + 8;
    const float base0 = fmaf(cJ, g_j1row[co0], cD);
    const float base1 = fmaf(cJ, g_j1row[co1], cD);
    const float a20 = g_a2[co0], b20 = g_b2v[co0];
    const float a21 = g_a2[co1], b21 = g_b2v[co1];

    float lmn = FMAXV, lmx = 0.f;
    #pragma unroll
    for (int t = 0; t < 8; t++) {
        int pl = t * 8 + (lane & 3) * 2;
        float kc0 = kcolF[pl], kc1 = kcolF[pl + 1];
        float y00 = fmaf(cS, __int2float_rn(acc[t][0]), fmaf(cK, kc0, base0));
        float y01 = fmaf(cS, __int2float_rn(acc[t][1]), fmaf(cK, kc1, base0));
        float y10 = fmaf(cS, __int2float_rn(acc[t][2]), fmaf(cK, kc0, base1));
        float y11 = fmaf(cS, __int2float_rn(acc[t][3]), fmaf(cK, kc1, base1));
        float h00 = fmaxf(fmaf(a20, y00, b20), 0.f);
        float h01 = fmaxf(fmaf(a20, y01, b20), 0.f);
        float h10 = fmaxf(fmaf(a21, y10, b21), 0.f);
        float h11 = fmaxf(fmaf(a21, y11, b21), 0.f);
        lmn = fminf(lmn, fminf(fminf(h00, h01), fminf(h10, h11)));
        lmx = fmaxf(lmx, fmaxf(fmaxf(h00, h01), fmaxf(h10, h11)));
        int px0 = col0 + pl;
        g_h2buf[px0 * C2 + co0]       = h00;
        g_h2buf[(px0 + 1) * C2 + co0] = h01;
        g_h2buf[px0 * C2 + co1]       = h10;
        g_h2buf[(px0 + 1) * C2 + co1] = h11;
    }
    float bm = wredmin(lmn), bM = wredmax(lmx);
    if (lane == 0) { smn[wid] = bm; smx[wid] = bM; }
    __syncthreads();
    if (wid == 0) {
        float m2 = (lane < 8) ? smn[lane] : FMAXV;
        float M2 = (lane < 8) ? smx[lane] : 0.f;
        m2 = wredmin(m2); M2 = wredmax(M2);
        if (lane == 0) {
            atomicMin(&g_h2mn, __float_as_uint(m2));
            atomicMax(&g_h2mx, __float_as_uint(M2));
        }
    }
}

// ---------------- 4.5: h2 -> u8 codes (8 threads/pixel, coalesced) ----------------
__global__ __launch_bounds__(256) void codes_k() {
    const int t = blockIdx.x * 256 + threadIdx.x;
    const int gp = t >> 3;       // pixel
    const int sub = t & 7;       // 16-channel group
    const float mn = __uint_as_float(g_h2mn);
    const float mx = __uint_as_float(g_h2mx);
    const float s = fmaxf((mx - mn) * (1.f / 255.f), 1e-8f);
    const float inv = 1.f / s;
    const float4* src = (const float4*)(g_h2buf + (size_t)gp * C2) + sub * 4;
    int ksum = 0;
    unsigned wds[4];
    #pragma unroll
    for (int j = 0; j < 4; j++) {
        float4 v = src[j];
        int c0 = __float2int_rn((v.x - mn) * inv);
        int c1 = __float2int_rn((v.y - mn) * inv);
        int c2 = __float2int_rn((v.z - mn) * inv);
        int c3 = __float2int_rn((v.w - mn) * inv);
        ksum += c0 + c1 + c2 + c3;
        wds[j] = (unsigned)c0 | ((unsigned)c1 << 8) | ((unsigned)c2 << 16) | ((unsigned)c3 << 24);
    }
    ((uint4*)(g_h2q + (size_t)gp * C2))[sub] = make_uint4(wds[0], wds[1], wds[2], wds[3]);
    ksum += __shfl_down_sync(0xffffffffu, ksum, 4, 8);
    ksum += __shfl_down_sync(0xffffffffu, ksum, 2, 8);
    ksum += __shfl_down_sync(0xffffffffu, ksum, 1, 8);
    if (sub == 0) g_T[gp] = (float)ksum;
}

// ---------------- 5: conv3x3 via u8 IMMA, smem-staged zero-padded codes ----------------
#define BP2 144
__global__ __launch_bounds__(224) void conv2_k(float* __restrict__ out) {
    __shared__ uint4 s_w[2304];                 // 36864 B
    __shared__ __align__(16) u8 s_b[4 * 30 * BP2];  // 17280 B, zero-padded halo
    __shared__ float s_T[4 * 28];
    __shared__ float s_K9[56];
    __shared__ float s_Jtap[C3 * 9];
    __shared__ float s_Jall[C3];

    const int tid = threadIdx.x;
    const int lane = tid & 31, wid = tid >> 5;
    const int n = blockIdx.y, sl = blockIdx.x;
    const int r0 = sl * 2;

    for (int f = tid; f < 2304; f += 224) s_w[f] = g_w2p[f];
    // stage codes: 4 rows (r0-1..r0+2) x 30 cols (-1..28), zero-padded
    for (int idx = tid; idx < 4 * 30 * 8; idx += 224) {
        int j = idx & 7;
        int slot = idx >> 3;
        int cc = slot % 30, l = slot / 30;
        int gr = r0 - 1 + l, gc = cc - 1;
        uint4 vv = make_uint4(0u, 0u, 0u, 0u);
        if ((unsigned)gr < 28u && (unsigned)gc < 28u)
            vv = *(const uint4*)(g_h2q + ((size_t)(n * 784 + gr * 28 + gc)) * C2 + j * 16);
        *(uint4*)(s_b + (size_t)slot * BP2 + j * 16) = vv;
    }
    for (int e = tid; e < 112; e += 224) {
        int rr = r0 - 1 + e / 28, cc = e - (e / 28) * 28;
        s_T[e] = ((unsigned)rr < 28u) ? g_T[n * 784 + rr * 28 + cc] : 0.f;
    }
    for (int e = tid; e < C3 * 9; e += 224) s_Jtap[e] = g_Jtap[e];
    if (tid < C3) s_Jall[tid] = g_Jall[tid];
    __syncthreads();
    if (tid < 56) {
        int rl = tid / 28, c = tid - rl * 28;
        float s = 0.f;
        #pragma unroll
        for (int dr = 0; dr < 3; dr++) {
            #pragma unroll
            for (int dc = -1; dc <= 1; dc++) {
                int cc = c + dc;
                if ((unsigned)cc < 28u) s += s_T[(rl + dr) * 28 + cc];
            }
        }
        s_K9[tid] = s;
    }
    __syncthreads();

    // B pixel for this lane
    const int ql = wid * 8 + (lane >> 2);
    const int rl = ql / 28, cl = ql - (ql / 28) * 28;

    int acc0[4] = {0, 0, 0, 0}, acc1[4] = {0, 0, 0, 0};

    #pragma unroll
    for (int t = 0; t < 9; t++) {
        const int dr = t / 3, dc = t % 3;     // smem-relative (0..2)
        const u8* bt = s_b + (size_t)((rl + dr) * 30 + (cl + dc)) * BP2 + (lane & 3) * 4;
        #pragma unroll
        for (int g = 0; g < 4; g++) {
            unsigned b0 = *(const unsigned*)(bt + g * 32);
            unsigned b1 = *(const unsigned*)(bt + g * 32 + 16);
            uint4 a0 = s_w[((t * 4 + g) * 2 + 0) * 32 + lane];
            mma_u8(acc0, a0.x, a0.y, a0.z, a0.w, b0, b1);
            uint4 a1 = s_w[((t * 4 + g) * 2 + 1) * 32 + lane];
            mma_u8(acc1, a1.x, a1.y, a1.z, a1.w, b0, b1);
        }
    }

    // epilogue
    const float mn2 = __uint_as_float(g_h2mn);
    const float mx2 = __uint_as_float(g_h2mx);
    const float s2 = fmaxf((mx2 - mn2) * (1.f / 255.f), 1e-8f);
    const float sw = g_w2s, mnw = g_w2mn;
    const float cS = sw * s2;
    const float cK = mnw * s2;
    const float cJ = sw * mn2;
    const float cD = 1152.f * mnw * mn2;

    const int qa = wid * 8 + 2 * (lane & 3);
    const int co_r = lane >> 2;

    #pragma unroll
    for (int e = 0; e < 2; e++) {
        const int q = qa + e;
        const float k9 = s_K9[q];
        const int r = r0 + q / 28, c = q - (q / 28) * 28;
        const bool border = (r == 0) | (r == 27) | (c == 0) | (c == 27);
        int npad = 0;
        float sj[4] = {0.f, 0.f, 0.f, 0.f};
        if (border) {
            #pragma unroll
            for (int t = 0; t < 9; t++) {
                const int dr = t / 3 - 1, dc = t % 3 - 1;
                const bool pad = ((unsigned)(r + dr) >= 28u) || ((unsigned)(c + dc) >= 28u);
                if (pad) {
                    npad++;
                    #pragma unroll
                    for (int m = 0; m < 4; m++) sj[m] += s_Jtap[(co_r + 8 * m) * 9 + t];
                }
            }
        }
        #pragma unroll
        for (int m = 0; m < 4; m++) {
            const int co = co_r + 8 * m;
            int S = (m == 0) ? acc0[0 + e] : (m == 1) ? acc0[2 + e] : (m == 2) ? acc1[0 + e] : acc1[2 + e];
            float y = fmaf(cS, __int2float_rn(S), fmaf(cK, k9, fmaf(cJ, s_Jall[co], cD)));
            if (border) y -= mn2 * fmaf(sw, sj[m], mnw * 128.f * (float)npad);
            out[(n * C3 + co) * HW + r * 28 + c] = y;
        }
    }
}

// ---------------- launch ----------------
extern "C" void kernel_launch(void* const* d_in, const int* in_sizes, int n_in,
                              void* d_out, int out_size) {
    const float* x  = (const float*)d_in[0];
    const float* g1 = (const float*)d_in[1];
    const float* b1 = (const float*)d_in[2];
    const float* m1 = (const float*)d_in[3];
    const float* v1 = (const float*)d_in[4];
    const float* w1 = (const float*)d_in[5];
    const float* g2 = (const float*)d_in[6];
    const float* b2 = (const float*)d_in[7];
    const float* m2 = (const float*)d_in[8];
    const float* v2 = (const float*)d_in[9];
    const float* w2 = (const float*)d_in[10];
    float* out = (float*)d_out;

    prep_k<<<1, 512>>>(g1, b1, m1, v1, g2, b2, m2, v2);
    wquant_k<<<2, 256>>>(w1, w2);
    h1mm_k<<<2048, 256>>>(x);
    conv1_k<<<NPIX / 64, 256>>>(x);
    codes_k<<<NPIX * 8 / 256, 256>>>();
    conv2_k<<<dim3(14, Nn), 224>>>(out);
}

// round 11
// speedup vs baseline: 3.3514x; 1.0966x over previous
#include <cuda_runtime.h>

typedef unsigned long long ull;
typedef unsigned char u8;

#define Nn 64
#define C1 512
#define C2 128
#define C3 32
#define HW 784
#define NPIX (Nn*HW)   // 50176

#define FMAXV 3.402823466e38f

// ---------------- device scratch ----------------
__device__ float g_a1[C1], g_b1v[C1], g_a2[C2], g_b2v[C2];
__device__ uint4 g_w1p[8*16*32];                // w1 u8 codes, mma-fragment-permuted
__device__ float g_j1row[C2];                   // per-co sum of w1 codes
__device__ uint4 g_w2p[2304];                   // w2 codes fragment-packed
__device__ float g_Jtap[C3*9];                  // per-(co,tap) code sums
__device__ float g_Jall[C3];                    // per-co total code sums
__device__ __align__(16) float g_h2buf[NPIX*C2];   // h2 pre-quant, [pixel][co] layout
__device__ __align__(16) u8    g_h2q[NPIX*C2];     // h2 u8 codes, [pixel][ci] layout
__device__ float g_T[NPIX];                        // per-pixel sum of codes
__device__ unsigned g_h1mn, g_h1mx, g_h2mn, g_h2mx;  // nonneg floats as uint bits
__device__ unsigned g_wmm[4];                   // monotone-mapped {w1mn,w1mx,w2mn,w2mx}

// ---------------- helpers ----------------
__device__ __forceinline__ void mma_u8(int* d, unsigned a0, unsigned a1, unsigned a2, unsigned a3,
                                       unsigned b0, unsigned b1) {
    asm volatile("mma.sync.aligned.m16n8k32.row.col.s32.u8.u8.s32 "
                 "{%0,%1,%2,%3},{%4,%5,%6,%7},{%8,%9},{%0,%1,%2,%3};"
                 : "+r"(d[0]), "+r"(d[1]), "+r"(d[2]), "+r"(d[3])
                 : "r"(a0), "r"(a1), "r"(a2), "r"(a3), "r"(b0), "r"(b1));
}
__device__ __forceinline__ float wredmin(float v) {
    #pragma unroll
    for (int o = 16; o > 0; o >>= 1) v = fminf(v, __shfl_xor_sync(0xffffffffu, v, o));
    return v;
}
__device__ __forceinline__ float wredmax(float v) {
    #pragma unroll
    for (int o = 16; o > 0; o >>= 1) v = fmaxf(v, __shfl_xor_sync(0xffffffffu, v, o));
    return v;
}
__device__ __forceinline__ float wredsum(float v) {
    #pragma unroll
    for (int o = 16; o > 0; o >>= 1) v += __shfl_xor_sync(0xffffffffu, v, o);
    return v;
}
// order-preserving float<->unsigned map (handles negatives)
__device__ __forceinline__ unsigned fmap(float f) {
    unsigned u = __float_as_uint(f);
    return (u & 0x80000000u) ? ~u : (u | 0x80000000u);
}
__device__ __forceinline__ float funmap(unsigned m) {
    return __uint_as_float((m & 0x80000000u) ? (m ^ 0x80000000u) : ~m);
}

// ---------------- 1: prep ----------------
__global__ void prep_k(const float* __restrict__ g1, const float* __restrict__ b1,
                       const float* __restrict__ m1, const float* __restrict__ v1,
                       const float* __restrict__ g2, const float* __restrict__ b2,
                       const float* __restrict__ m2, const float* __restrict__ v2) {
    int t = threadIdx.x;
    if (t == 0) {
        g_h1mn = 0x7f7fffffu; g_h1mx = 0u; g_h2mn = 0x7f7fffffu; g_h2mx = 0u;
        g_wmm[0] = 0xFFFFFFFFu; g_wmm[1] = 0u; g_wmm[2] = 0xFFFFFFFFu; g_wmm[3] = 0u;
    }
    if (t < C1) {
        float inv = g1[t] / sqrtf(v1[t] + 1e-5f);
        g_a1[t] = inv; g_b1v[t] = b1[t] - m1[t] * inv;
    }
    if (t < C2) {
        float inv = g2[t] / sqrtf(v2[t] + 1e-5f);
        g_a2[t] = inv; g_b2v[t] = b2[t] - m2[t] * inv;
    }
}

// ---------------- 2a: weight min/max (parallel, atomics) ----------------
// blocks 0..15: w1 (16 x 4096 = 65536); blocks 16..23: w2 (8 x 4608 = 36864)
__global__ void wmm_k(const float* __restrict__ w1, const float* __restrict__ w2) {
    __shared__ float smn[8], smx[8];
    const int b = blockIdx.x, t = threadIdx.x;
    const float* w; int cnt, slot;
    if (b < 16) { w = w1 + b * 4096; cnt = 4096; slot = 0; }
    else        { w = w2 + (b - 16) * 4608; cnt = 4608; slot = 2; }
    float mn = FMAXV, mx = -FMAXV;
    for (int i = t; i < cnt; i += 256) { float v = w[i]; mn = fminf(mn, v); mx = fmaxf(mx, v); }
    float bm = wredmin(mn), bM = wredmax(mx);
    int wd = t >> 5, ln = t & 31;
    if (ln == 0) { smn[wd] = bm; smx[wd] = bM; }
    __syncthreads();
    if (wd == 0) {
        float m2 = (ln < 8) ? smn[ln] : FMAXV;
        float M2 = (ln < 8) ? smx[ln] : -FMAXV;
        m2 = wredmin(m2); M2 = wredmax(M2);
        if (ln == 0) {
            atomicMin(&g_wmm[slot], fmap(m2));
            atomicMax(&g_wmm[slot + 1], fmap(M2));
        }
    }
}

// ---------------- 2b: weight pack (parallel) ----------------
// blocks 0..15: w1 fragment pack (256 frags each) + j1row (8 co each)
// block 16: w2 codes + Jtap + Jall + fragment pack
__global__ void wpack_k(const float* __restrict__ w1, const float* __restrict__ w2) {
    const int b = blockIdx.x, t = threadIdx.x;
    if (b < 16) {
        const float mnv = funmap(g_wmm[0]);
        const float sc = fmaxf((funmap(g_wmm[1]) - mnv) * (1.f / 255.f), 1e-8f);
        // fragment pack: one frag per thread
        {
            int f = b * 256 + t;
            int m = f >> 9;
            int rem = f & 511;
            int q = rem >> 5, L = rem & 31;
            unsigned rg[4];
            #pragma unroll
            for (int r = 0; r < 4; r++) {
                int row = m * 16 + (L >> 2) + (r & 1) * 8;
                int kc = q * 32 + (r >> 1) * 16 + (L & 3) * 4;
                unsigned u = 0;
                #pragma unroll
                for (int i = 0; i < 4; i++) {
                    int code = __float2int_rn(__fdiv_rn(w1[row * C1 + kc + i] - mnv, sc));
                    u |= ((unsigned)code & 0xffu) << (8 * i);
                }
                rg[r] = u;
            }
            g_w1p[f] = make_uint4(rg[0], rg[1], rg[2], rg[3]);
        }
        // j1row: warp w handles co = b*8 + w
        {
            int wd = t >> 5, ln = t & 31;
            int co = b * 8 + wd;
            float s = 0.f;
            #pragma unroll
            for (int i = 0; i < 16; i++)
                s += (float)__float2int_rn(__fdiv_rn(w1[co * C1 + i * 32 + ln] - mnv, sc));
            s = wredsum(s);
            if (ln == 0) g_j1row[co] = s;
        }
    } else {
        __shared__ u8 s_code[C3 * C2 * 9];
        const float mnv = funmap(g_wmm[2]);
        const float sc = fmaxf((funmap(g_wmm[3]) - mnv) * (1.f / 255.f), 1e-8f);
        for (int i = t; i < C3 * C2 * 9; i += 256)
            s_code[i] = (u8)__float2int_rn(__fdiv_rn(w2[i] - mnv, sc));
        __syncthreads();
        for (int e = t; e < C3 * 9; e += 256) {
            int co = e / 9, tap = e - co * 9;
            int s = 0;
            for (int ci = 0; ci < C2; ci++) s += s_code[(co * C2 + ci) * 9 + tap];
            g_Jtap[e] = (float)s;
        }
        if (t < C3) {
            int s = 0;
            for (int i = 0; i < C2 * 9; i++) s += s_code[t * C2 * 9 + i];
            g_Jall[t] = (float)s;
        }
        for (int f = t; f < 2304; f += 256) {
            int lane = f & 31;
            int u = f >> 5;
            int mtile = u & 1;
            int v2i = u >> 1;
            int g = v2i & 3, tap = v2i >> 2;
            int co_b = mtile * 16 + (lane >> 2);
            int ci_b = g * 32 + (lane & 3) * 4;
            unsigned rg[4];
            #pragma unroll
            for (int r = 0; r < 4; r++) {
                int co = co_b + (r & 1) * 8;
                int ci0 = ci_b + (r >> 1) * 16;
                unsigned uu = 0;
                #pragma unroll
                for (int i = 0; i < 4; i++)
                    uu |= ((unsigned)s_code[(co * C2 + ci0 + i) * 9 + tap]) << (8 * i);
                rg[r] = uu;
            }
            g_w2p[f] = make_uint4(rg[0], rg[1], rg[2], rg[3]);
        }
    }
}

// ---------------- 3: global min/max of relu(BN1(x)) ----------------
__global__ void h1mm_k(const float* __restrict__ x) {
    const int NV = Nn * C1 * HW / 4;
    float mn = FMAXV, mx = 0.f;
    for (int v = blockIdx.x * blockDim.x + threadIdx.x; v < NV; v += gridDim.x * blockDim.x) {
        int ci = (v / 196) & 511;
        float4 p = ((const float4*)x)[v];
        float a = g_a1[ci], b = g_b1v[ci];
        float h0 = fmaxf(fmaf(a, p.x, b), 0.f);
        float h1 = fmaxf(fmaf(a, p.y, b), 0.f);
        float h2 = fmaxf(fmaf(a, p.z, b), 0.f);
        float h3 = fmaxf(fmaf(a, p.w, b), 0.f);
        mn = fminf(mn, fminf(fminf(h0, h1), fminf(h2, h3)));
        mx = fmaxf(mx, fmaxf(fmaxf(h0, h1), fmaxf(h2, h3)));
    }
    __shared__ float smn[8], smx[8];
    float bm = wredmin(mn), bM = wredmax(mx);
    int w = threadIdx.x >> 5, ln = threadIdx.x & 31;
    if (ln == 0) { smn[w] = bm; smx[w] = bM; }
    __syncthreads();
    if (w == 0) {
        float m2 = (ln < 8) ? smn[ln] : FMAXV;
        float M2 = (ln < 8) ? smx[ln] : 0.f;
        m2 = wredmin(m2); M2 = wredmax(M2);
        if (ln == 0) {
            atomicMin(&g_h1mn, __float_as_uint(m2));
            atomicMax(&g_h1mx, __float_as_uint(M2));
        }
    }
}

// ---------------- 4: conv1x1 via u8 IMMA, k32 chunks, 4 CTAs/SM ----------------
#define BP1 48
#define BUF1 (64*BP1)   // 3072 B
__global__ __launch_bounds__(256, 4) void conv1_k(const float* __restrict__ x) {
    __shared__ __align__(16) u8 Bs[2 * BUF1];
    __shared__ int kcp[4][64];
    __shared__ float kcolF[64];
    __shared__ float sa1[C1], sb1[C1];
    __shared__ float smn[8], smx[8];

    const int tid = threadIdx.x;
    const int lane = tid & 31, wid = tid >> 5;
    const int col0 = blockIdx.x * 64;

    #pragma unroll
    for (int l = 0; l < 2; l++) {
        int e = tid + l * 256;
        sa1[e] = g_a1[e]; sb1[e] = g_b1v[e];
    }

    const float mn1 = __uint_as_float(g_h1mn);
    const float mx1 = __uint_as_float(g_h1mx);
    const float s1 = fmaxf((mx1 - mn1) * (1.f / 255.f), 1e-8f);
    const float i1 = 1.f / s1;

    const int pB = tid & 63;
    const int tq = tid >> 6;        // ci-octet within chunk
    const int gpB = col0 + pB;
    const int nimgB = gpB / 784;
    const float* xb = x + nimgB * C1 * HW + (gpB - nimgB * 784) + tq * 8 * HW;

    int acc[8][4];
    #pragma unroll
    for (int t = 0; t < 8; t++)
        #pragma unroll
        for (int r = 0; r < 4; r++) acc[t][r] = 0;

    float v[8];
    int ksum = 0;
    #pragma unroll
    for (int j = 0; j < 8; j++) v[j] = xb[j * HW];
    __syncthreads();   // sa1/sb1 ready

    // produce chunk 0
    {
        const int cib = tq * 8;
        #pragma unroll
        for (int s = 0; s < 2; s++) {
            unsigned u = 0;
            #pragma unroll
            for (int j = 0; j < 4; j++) {
                int ci = cib + s * 4 + j;
                float h = fmaxf(fmaf(sa1[ci], v[s * 4 + j], sb1[ci]), 0.f);
                int code = __float2int_rn((h - mn1) * i1);
                ksum += code;
                u |= ((unsigned)code & 0xffu) << (8 * j);
            }
            *(unsigned*)(Bs + pB * BP1 + tq * 8 + s * 4) = u;
        }
    }
    // prefetch chunk 1
    #pragma unroll
    for (int j = 0; j < 8; j++) v[j] = xb[(32 + j) * HW];
    __syncthreads();

    for (int c = 0; c < 16; c++) {
        const u8* curB = Bs + (c & 1) * BUF1;
        if (c < 15) {
            u8* nxtB = Bs + ((c + 1) & 1) * BUF1;
            const int cib = (c + 1) * 32 + tq * 8;
            #pragma unroll
            for (int s = 0; s < 2; s++) {
                unsigned u = 0;
                #pragma unroll
                for (int j = 0; j < 4; j++) {
                    int ci = cib + s * 4 + j;
                    float h = fmaxf(fmaf(sa1[ci], v[s * 4 + j], sb1[ci]), 0.f);
                    int code = __float2int_rn((h - mn1) * i1);
                    ksum += code;
                    u |= ((unsigned)code & 0xffu) << (8 * j);
                }
                *(unsigned*)(nxtB + pB * BP1 + tq * 8 + s * 4) = u;
            }
            if (c < 14) {
                #pragma unroll
                for (int j = 0; j < 8; j++) v[j] = xb[((c + 2) * 32 + j) * HW];
            }
        }
        {
            uint4 a = g_w1p[(wid * 16 + c) * 32 + lane];
            const u8* bbase = curB + (lane >> 2) * BP1 + (lane & 3) * 4;
            #pragma unroll
            for (int t = 0; t < 8; t++) {
                unsigned b0 = *(const unsigned*)(bbase + t * 8 * BP1);
                unsigned b1 = *(const unsigned*)(bbase + t * 8 * BP1 + 16);
                mma_u8(acc[t], a.x, a.y, a.z, a.w, b0, b1);
            }
        }
        __syncthreads();
    }

    kcp[tq][pB] = ksum;
    __syncthreads();
    if (tid < 64) kcolF[tid] = (float)(kcp[0][tid] + kcp[1][tid] + kcp[2][tid] + kcp[3][tid]);
    __syncthreads();

    const float mnv = funmap(g_wmm[0]);
    const float sw = fmaxf((funmap(g_wmm[1]) - mnv) * (1.f / 255.f), 1e-8f);
    const float cS = sw * s1;
    const float cK = mnv * s1;
    const float cJ = sw * mn1;
    const float cD = 512.f * mnv * mn1;

    const int g = lane >> 2;
    const int co0 = wid * 16 + g, co1 = co0 + 8;
    const float base0 = fmaf(cJ, g_j1row[co0], cD);
    const float base1 = fmaf(cJ, g_j1row[co1], cD);
    const float a20 = g_a2[co0], b20 = g_b2v[co0];
    const float a21 = g_a2[co1], b21 = g_b2v[co1];

    float lmn = FMAXV, lmx = 0.f;
    #pragma unroll
    for (int t = 0; t < 8; t++) {
        int pl = t * 8 + (lane & 3) * 2;
        float kc0 = kcolF[pl], kc1 = kcolF[pl + 1];
        float y00 = fmaf(cS, __int2float_rn(acc[t][0]), fmaf(cK, kc0, base0));
        float y01 = fmaf(cS, __int2float_rn(acc[t][1]), fmaf(cK, kc1, base0));
        float y10 = fmaf(cS, __int2float_rn(acc[t][2]), fmaf(cK, kc0, base1));
        float y11 = fmaf(cS, __int2float_rn(acc[t][3]), fmaf(cK, kc1, base1));
        float h00 = fmaxf(fmaf(a20, y00, b20), 0.f);
        float h01 = fmaxf(fmaf(a20, y01, b20), 0.f);
        float h10 = fmaxf(fmaf(a21, y10, b21), 0.f);
        float h11 = fmaxf(fmaf(a21, y11, b21), 0.f);
        lmn = fminf(lmn, fminf(fminf(h00, h01), fminf(h10, h11)));
        lmx = fmaxf(lmx, fmaxf(fmaxf(h00, h01), fmaxf(h10, h11)));
        int px0 = col0 + pl;
        g_h2buf[px0 * C2 + co0]       = h00;
        g_h2buf[(px0 + 1) * C2 + co0] = h01;
        g_h2buf[px0 * C2 + co1]       = h10;
        g_h2buf[(px0 + 1) * C2 + co1] = h11;
    }
    float bm = wredmin(lmn), bM = wredmax(lmx);
    if (lane == 0) { smn[wid] = bm; smx[wid] = bM; }
    __syncthreads();
    if (wid == 0) {
        float m2 = (lane < 8) ? smn[lane] : FMAXV;
        float M2 = (lane < 8) ? smx[lane] : 0.f;
        m2 = wredmin(m2); M2 = wredmax(M2);
        if (lane == 0) {
            atomicMin(&g_h2mn, __float_as_uint(m2));
            atomicMax(&g_h2mx, __float_as_uint(M2));
        }
    }
}

// ---------------- 4.5: h2 -> u8 codes (8 threads/pixel, coalesced) ----------------
__global__ __launch_bounds__(256) void codes_k() {
    const int t = blockIdx.x * 256 + threadIdx.x;
    const int gp = t >> 3;
    const int sub = t & 7;
    const float mn = __uint_as_float(g_h2mn);
    const float mx = __uint_as_float(g_h2mx);
    const float s = fmaxf((mx - mn) * (1.f / 255.f), 1e-8f);
    const float inv = 1.f / s;
    const float4* src = (const float4*)(g_h2buf + (size_t)gp * C2) + sub * 4;
    int ksum = 0;
    unsigned wds[4];
    #pragma unroll
    for (int j = 0; j < 4; j++) {
        float4 v = src[j];
        int c0 = __float2int_rn((v.x - mn) * inv);
        int c1 = __float2int_rn((v.y - mn) * inv);
        int c2 = __float2int_rn((v.z - mn) * inv);
        int c3 = __float2int_rn((v.w - mn) * inv);
        ksum += c0 + c1 + c2 + c3;
        wds[j] = (unsigned)c0 | ((unsigned)c1 << 8) | ((unsigned)c2 << 16) | ((unsigned)c3 << 24);
    }
    ((uint4*)(g_h2q + (size_t)gp * C2))[sub] = make_uint4(wds[0], wds[1], wds[2], wds[3]);
    ksum += __shfl_down_sync(0xffffffffu, ksum, 4, 8);
    ksum += __shfl_down_sync(0xffffffffu, ksum, 2, 8);
    ksum += __shfl_down_sync(0xffffffffu, ksum, 1, 8);
    if (sub == 0) g_T[gp] = (float)ksum;
}

// ---------------- 5: conv3x3 via u8 IMMA, smem-staged zero-padded codes ----------------
#define BP2 144
__global__ __launch_bounds__(224) void conv2_k(float* __restrict__ out) {
    __shared__ uint4 s_w[2304];
    __shared__ __align__(16) u8 s_b[4 * 30 * BP2];
    __shared__ float s_T[4 * 28];
    __shared__ float s_K9[56];
    __shared__ float s_Jtap[C3 * 9];
    __shared__ float s_Jall[C3];

    const int tid = threadIdx.x;
    const int lane = tid & 31, wid = tid >> 5;
    const int n = blockIdx.y, sl = blockIdx.x;
    const int r0 = sl * 2;

    for (int f = tid; f < 2304; f += 224) s_w[f] = g_w2p[f];
    for (int idx = tid; idx < 4 * 30 * 8; idx += 224) {
        int j = idx & 7;
        int slot = idx >> 3;
        int cc = slot % 30, l = slot / 30;
        int gr = r0 - 1 + l, gc = cc - 1;
        uint4 vv = make_uint4(0u, 0u, 0u, 0u);
        if ((unsigned)gr < 28u && (unsigned)gc < 28u)
            vv = *(const uint4*)(g_h2q + ((size_t)(n * 784 + gr * 28 + gc)) * C2 + j * 16);
        *(uint4*)(s_b + (size_t)slot * BP2 + j * 16) = vv;
    }
    for (int e = tid; e < 112; e += 224) {
        int rr = r0 - 1 + e / 28, cc = e - (e / 28) * 28;
        s_T[e] = ((unsigned)rr < 28u) ? g_T[n * 784 + rr * 28 + cc] : 0.f;
    }
    for (int e = tid; e < C3 * 9; e += 224) s_Jtap[e] = g_Jtap[e];
    if (tid < C3) s_Jall[tid] = g_Jall[tid];
    __syncthreads();
    if (tid < 56) {
        int rl = tid / 28, c = tid - rl * 28;
        float s = 0.f;
        #pragma unroll
        for (int dr = 0; dr < 3; dr++) {
            #pragma unroll
            for (int dc = -1; dc <= 1; dc++) {
                int cc = c + dc;
                if ((unsigned)cc < 28u) s += s_T[(rl + dr) * 28 + cc];
            }
        }
        s_K9[tid] = s;
    }
    __syncthreads();

    const int ql = wid * 8 + (lane >> 2);
    const int rl = ql / 28, cl = ql - (ql / 28) * 28;

    int acc0[4] = {0, 0, 0, 0}, acc1[4] = {0, 0, 0, 0};

    #pragma unroll
    for (int t = 0; t < 9; t++) {
        const int dr = t / 3, dc = t % 3;
        const u8* bt = s_b + (size_t)((rl + dr) * 30 + (cl + dc)) * BP2 + (lane & 3) * 4;
        #pragma unroll
        for (int g = 0; g < 4; g++) {
            unsigned b0 = *(const unsigned*)(bt + g * 32);
            unsigned b1 = *(const unsigned*)(bt + g * 32 + 16);
            uint4 a0 = s_w[((t * 4 + g) * 2 + 0) * 32 + lane];
            mma_u8(acc0, a0.x, a0.y, a0.z, a0.w, b0, b1);
            uint4 a1 = s_w[((t * 4 + g) * 2 + 1) * 32 + lane];
            mma_u8(acc1, a1.x, a1.y, a1.z, a1.w, b0, b1);
        }
    }

    const float mn2 = __uint_as_float(g_h2mn);
    const float mx2 = __uint_as_float(g_h2mx);
    const float s2 = fmaxf((mx2 - mn2) * (1.f / 255.f), 1e-8f);
    const float mnv = funmap(g_wmm[2]);
    const float sw = fmaxf((funmap(g_wmm[3]) - mnv) * (1.f / 255.f), 1e-8f);
    const float cS = sw * s2;
    const float cK = mnv * s2;
    const float cJ = sw * mn2;
    const float cD = 1152.f * mnv * mn2;

    const int qa = wid * 8 + 2 * (lane & 3);
    const int co_r = lane >> 2;

    #pragma unroll
    for (int e = 0; e < 2; e++) {
        const int q = qa + e;
        const float k9 = s_K9[q];
        const int r = r0 + q / 28, c = q - (q / 28) * 28;
        const bool border = (r == 0) | (r == 27) | (c == 0) | (c == 27);
        int npad = 0;
        float sj[4] = {0.f, 0.f, 0.f, 0.f};
        if (border) {
            #pragma unroll
            for (int t = 0; t < 9; t++) {
                const int dr = t / 3 - 1, dc = t % 3 - 1;
                const bool pad = ((unsigned)(r + dr) >= 28u) || ((unsigned)(c + dc) >= 28u);
                if (pad) {
                    npad++;
                    #pragma unroll
                    for (int m = 0; m < 4; m++) sj[m] += s_Jtap[(co_r + 8 * m) * 9 + t];
                }
            }
        }
        #pragma unroll
        for (int m = 0; m < 4; m++) {
            const int co = co_r + 8 * m;
            int S = (m == 0) ? acc0[0 + e] : (m == 1) ? acc0[2 + e] : (m == 2) ? acc1[0 + e] : acc1[2 + e];
            float y = fmaf(cS, __int2float_rn(S), fmaf(cK, k9, fmaf(cJ, s_Jall[co], cD)));
            if (border) y -= mn2 * fmaf(sw, sj[m], mnv * 128.f * (float)npad);
            out[(n * C3 + co) * HW + r * 28 + c] = y;
        }
    }
}

// ---------------- launch ----------------
extern "C" void kernel_launch(void* const* d_in, const int* in_sizes, int n_in,
                              void* d_out, int out_size) {
    const float* x  = (const float*)d_in[0];
    const float* g1 = (const float*)d_in[1];
    const float* b1 = (const float*)d_in[2];
    const float* m1 = (const float*)d_in[3];
    const float* v1 = (const float*)d_in[4];
    const float* w1 = (const float*)d_in[5];
    const float* g2 = (const float*)d_in[6];
    const float* b2 = (const float*)d_in[7];
    const float* m2 = (const float*)d_in[8];
    const float* v2 = (const float*)d_in[9];
    const float* w2 = (const float*)d_in[10];
    float* out = (float*)d_out;

    prep_k<<<1, 512>>>(g1, b1, m1, v1, g2, b2, m2, v2);
    wmm_k<<<24, 256>>>(w1, w2);
    wpack_k<<<17, 256>>>(w1, w2);
    h1mm_k<<<2048, 256>>>(x);
    conv1_k<<<NPIX / 64, 256>>>(x);
    codes_k<<<NPIX * 8 / 256, 256>>>();
    conv2_k<<<dim3(14, Nn), 224>>>(out);
}